// round 2
// baseline (speedup 1.0000x reference)
#include <cuda_runtime.h>
#include <cuda_bf16.h>
#include <cstdint>
#include <cstddef>

// Problem constants
#define B_  16
#define C1_ 128
#define C2_ 256
#define KK_ 4
#define H_  80
#define W_  80
#define P_  (H_*W_)           // 6400
#define EPS_ 1e-5f

// Scratch (device globals; no allocation allowed)
__device__ float g_y[B_*C2_*P_];          // post conv1+bn+silu   (~104.9 MB)
__device__ float g_mu[B_*C2_];
__device__ float g_rstd[B_*C2_];
__device__ float g_attn[B_*KK_];
__device__ float g_aggw[B_*C2_*C2_*9];    // per-sample weights    (~37.7 MB)
__device__ float g_aggb[B_*C2_];

// ---------------------------------------------------------------------------
// K1: y = silu(bn(conv1x1(x)))   GEMM per-sample: Y[o,p] = sum_c W[o,c]X[c,p]
// Tile 64(o) x 64(p) x 32(c); 256 threads; 4x4 microtile.
// ---------------------------------------------------------------------------
__global__ __launch_bounds__(256)
void k1_conv1(const float* __restrict__ x, const float* __restrict__ w,
              const float* __restrict__ bng, const float* __restrict__ bnb,
              const float* __restrict__ bnm, const float* __restrict__ bnv)
{
    __shared__ float As[32][68];   // [c][o], padded
    __shared__ float Bs[32][68];   // [c][p], padded

    const int b  = blockIdx.z;
    const int o0 = blockIdx.y * 64;
    const int p0 = blockIdx.x * 64;
    const int tid = threadIdx.x;
    const int tx = tid & 15, ty = tid >> 4;

    float acc[4][4];
#pragma unroll
    for (int j = 0; j < 4; ++j)
#pragma unroll
        for (int i = 0; i < 4; ++i) acc[j][i] = 0.f;

    for (int c0 = 0; c0 < C1_; c0 += 32) {
        // W tile: 64 o x 32 c = 2048 floats
#pragma unroll
        for (int r = 0; r < 8; ++r) {
            int l = tid + 256*r;
            int o = l >> 5, c = l & 31;
            As[c][o] = w[(o0+o)*C1_ + c0 + c];
        }
        // X tile: 32 c x 64 p = 512 float4
#pragma unroll
        for (int r = 0; r < 2; ++r) {
            int l = tid + 256*r;
            int c = l >> 4, p4 = l & 15;
            float4 v = *(const float4*)(x + ((size_t)(b*C1_ + c0 + c))*P_ + p0 + p4*4);
            *(float4*)&Bs[c][p4*4] = v;
        }
        __syncthreads();
#pragma unroll
        for (int kk = 0; kk < 32; ++kk) {
            float4 av = *(const float4*)&As[kk][ty*4];
            float4 bv = *(const float4*)&Bs[kk][tx*4];
            float ar[4] = {av.x, av.y, av.z, av.w};
            float br[4] = {bv.x, bv.y, bv.z, bv.w};
#pragma unroll
            for (int j = 0; j < 4; ++j)
#pragma unroll
                for (int i = 0; i < 4; ++i) acc[j][i] += ar[j]*br[i];
        }
        __syncthreads();
    }

#pragma unroll
    for (int j = 0; j < 4; ++j) {
        int o = o0 + ty*4 + j;
        float s = bng[o] * rsqrtf(bnv[o] + EPS_);
        float t = bnb[o] - bnm[o]*s;
        float4 r;
        float vv;
        vv = acc[j][0]*s + t; r.x = vv / (1.f + expf(-vv));
        vv = acc[j][1]*s + t; r.y = vv / (1.f + expf(-vv));
        vv = acc[j][2]*s + t; r.z = vv / (1.f + expf(-vv));
        vv = acc[j][3]*s + t; r.w = vv / (1.f + expf(-vv));
        *(float4*)&g_y[((size_t)(b*C2_ + o))*P_ + p0 + tx*4] = r;
    }
}

// ---------------------------------------------------------------------------
// K2: per (b,c) mean / rstd over 6400 spatial positions (mean == GAP pooled)
// ---------------------------------------------------------------------------
__global__ __launch_bounds__(256)
void k2_stats()
{
    const int bc = blockIdx.x;                 // 0..B*C2-1
    const float* p = g_y + (size_t)bc * P_;
    float s = 0.f, s2 = 0.f;
    for (int i = threadIdx.x; i < P_; i += 256) {
        float v = p[i];
        s += v; s2 += v*v;
    }
    __shared__ float sh[8], sh2[8];
    const int lane = threadIdx.x & 31, wid = threadIdx.x >> 5;
#pragma unroll
    for (int off = 16; off; off >>= 1) {
        s  += __shfl_down_sync(0xffffffffu, s,  off);
        s2 += __shfl_down_sync(0xffffffffu, s2, off);
    }
    if (lane == 0) { sh[wid] = s; sh2[wid] = s2; }
    __syncthreads();
    if (threadIdx.x == 0) {
        float t = 0.f, t2 = 0.f;
#pragma unroll
        for (int i = 0; i < 8; ++i) { t += sh[i]; t2 += sh2[i]; }
        float mu  = t  * (1.f / P_);
        float var = t2 * (1.f / P_) - mu*mu;
        g_mu[bc]   = mu;
        g_rstd[bc] = rsqrtf(fmaxf(var, 0.f) + EPS_);
    }
}

// ---------------------------------------------------------------------------
// K3: attention: relu(pooled@fc1^T+b1) -> @fc2^T+b2 -> softmax over K=4
// one warp per sample
// ---------------------------------------------------------------------------
__global__ void k3_attn(const float* __restrict__ fc1w, const float* __restrict__ fc1b,
                        const float* __restrict__ fc2w, const float* __restrict__ fc2b)
{
    const int b = blockIdx.x, lane = threadIdx.x;
    float s0 = 0.f, s1 = 0.f, s2 = 0.f, s3 = 0.f;
    for (int c = lane; c < C2_; c += 32) {
        float pv = g_mu[b*C2_ + c];
        s0 += pv * fc1w[0*C2_ + c];
        s1 += pv * fc1w[1*C2_ + c];
        s2 += pv * fc1w[2*C2_ + c];
        s3 += pv * fc1w[3*C2_ + c];
    }
#pragma unroll
    for (int off = 16; off; off >>= 1) {
        s0 += __shfl_down_sync(0xffffffffu, s0, off);
        s1 += __shfl_down_sync(0xffffffffu, s1, off);
        s2 += __shfl_down_sync(0xffffffffu, s2, off);
        s3 += __shfl_down_sync(0xffffffffu, s3, off);
    }
    if (lane == 0) {
        float a[4];
        a[0] = fmaxf(s0 + fc1b[0], 0.f);
        a[1] = fmaxf(s1 + fc1b[1], 0.f);
        a[2] = fmaxf(s2 + fc1b[2], 0.f);
        a[3] = fmaxf(s3 + fc1b[3], 0.f);
        float l[4];
#pragma unroll
        for (int j = 0; j < 4; ++j)
            l[j] = a[0]*fc2w[j*4+0] + a[1]*fc2w[j*4+1] + a[2]*fc2w[j*4+2] + a[3]*fc2w[j*4+3] + fc2b[j];
        float m = fmaxf(fmaxf(l[0], l[1]), fmaxf(l[2], l[3]));
        float e[4], den = 0.f;
#pragma unroll
        for (int j = 0; j < 4; ++j) { e[j] = expf(l[j] - m); den += e[j]; }
        float inv = 1.f / den;
#pragma unroll
        for (int j = 0; j < 4; ++j) g_attn[b*4 + j] = e[j] * inv;
    }
}

// ---------------------------------------------------------------------------
// K4a: agg_w[b] = sum_k attn[b,k] * dy_w[k]   (float4 elementwise)
// ---------------------------------------------------------------------------
__global__ __launch_bounds__(256)
void k4_aggw(const float* __restrict__ dyw)
{
    const int per_b4 = C2_*C2_*9/4;    // 147456
    int idx = blockIdx.x*256 + threadIdx.x;   // exactly B_*per_b4 threads
    int b = idx / per_b4;
    int r = idx - b*per_b4;
    float a0 = g_attn[b*4+0], a1 = g_attn[b*4+1], a2 = g_attn[b*4+2], a3 = g_attn[b*4+3];
    const float4* dw = (const float4*)dyw;
    float4 v0 = dw[r];
    float4 v1 = dw[per_b4   + r];
    float4 v2 = dw[2*per_b4 + r];
    float4 v3 = dw[3*per_b4 + r];
    float4 o;
    o.x = a0*v0.x + a1*v1.x + a2*v2.x + a3*v3.x;
    o.y = a0*v0.y + a1*v1.y + a2*v2.y + a3*v3.y;
    o.z = a0*v0.z + a1*v1.z + a2*v2.z + a3*v3.z;
    o.w = a0*v0.w + a1*v1.w + a2*v2.w + a3*v3.w;
    ((float4*)g_aggw)[idx] = o;
}

// K4b: agg_b[b,o] = sum_k attn[b,k] * dy_b[k,o]
__global__ void k4_aggb(const float* __restrict__ dyb)
{
    int idx = blockIdx.x*256 + threadIdx.x;   // B_*C2_ = 4096
    int b = idx >> 8, o = idx & 255;
    float v = 0.f;
#pragma unroll
    for (int k = 0; k < 4; ++k) v += g_attn[b*4+k] * dyb[k*C2_ + o];
    g_aggb[idx] = v;
}

// ---------------------------------------------------------------------------
// K5: per-sample 3x3 conv on instance-normalized y (norm fused into loads),
//     + agg bias + bn1.  Block: (b, 32 out-ch, 16x16 spatial tile).
// ---------------------------------------------------------------------------
__global__ __launch_bounds__(256)
void k5_dyconv(const float* __restrict__ g1, const float* __restrict__ b1,
               const float* __restrict__ m1, const float* __restrict__ v1,
               float* __restrict__ out)
{
    __shared__ float patch[18*18];
    __shared__ float wsm[32][12];      // 9 used, padded to 12 for aligned float4

    const int b    = blockIdx.z;
    const int o0   = blockIdx.y * 32;
    const int tile = blockIdx.x;       // 0..24
    const int h0 = (tile / 5) * 16;
    const int w0 = (tile % 5) * 16;
    const int tid = threadIdx.x;
    const int px = tid & 15, py = tid >> 4;

    float acc[32];
#pragma unroll
    for (int i = 0; i < 32; ++i) acc[i] = 0.f;

    const float* yb = g_y    + (size_t)b*C2_*P_;
    const float* wb = g_aggw + (size_t)b*C2_*C2_*9;

    for (int ci = 0; ci < C2_; ++ci) {
        const float cmu = __ldg(&g_mu[b*C2_ + ci]);
        const float cr  = __ldg(&g_rstd[b*C2_ + ci]);
        const float* yc = yb + (size_t)ci * P_;
        // 18x18 normalized patch with zero halo
        for (int idx = tid; idx < 324; idx += 256) {
            int r = idx / 18, c = idx - r*18;
            int gh = h0 + r - 1, gw = w0 + c - 1;
            float v = 0.f;
            if (gh >= 0 && gh < H_ && gw >= 0 && gw < W_)
                v = (yc[gh*W_ + gw] - cmu) * cr;
            patch[idx] = v;
        }
        // 32 x 9 weights for this input channel (288 > 256 threads: strided loop!)
        for (int idx = tid; idx < 288; idx += 256) {
            int o = idx / 9, q = idx - o*9;
            wsm[o][q] = wb[((size_t)(o0+o)*C2_ + ci)*9 + q];
        }
        __syncthreads();

        const float p0 = patch[py*18 + px],     pA = patch[py*18 + px + 1],     pB = patch[py*18 + px + 2];
        const float p3 = patch[(py+1)*18 + px], p4 = patch[(py+1)*18 + px + 1], p5 = patch[(py+1)*18 + px + 2];
        const float p6 = patch[(py+2)*18 + px], p7 = patch[(py+2)*18 + px + 1], p8 = patch[(py+2)*18 + px + 2];
#pragma unroll
        for (int oo = 0; oo < 32; ++oo) {
            float4 wa = *(const float4*)&wsm[oo][0];
            float4 wbv = *(const float4*)&wsm[oo][4];
            float  w8 = wsm[oo][8];
            acc[oo] += p0*wa.x + pA*wa.y + pB*wa.z + p3*wa.w
                     + p4*wbv.x + p5*wbv.y + p6*wbv.z + p7*wbv.w + p8*w8;
        }
        __syncthreads();
    }

    const int h = h0 + py, w = w0 + px;
#pragma unroll
    for (int oo = 0; oo < 32; ++oo) {
        int o = o0 + oo;
        float s = __ldg(&g1[o]) * rsqrtf(__ldg(&v1[o]) + EPS_);
        float res = (acc[oo] + __ldg(&g_aggb[b*C2_ + o]) - __ldg(&m1[o])) * s + __ldg(&b1[o]);
        out[((size_t)(b*C2_ + o))*P_ + h*W_ + w] = res;
    }
}

// ---------------------------------------------------------------------------
extern "C" void kernel_launch(void* const* d_in, const int* in_sizes, int n_in,
                              void* d_out, int out_size)
{
    const float* x      = (const float*)d_in[0];
    const float* conv1w = (const float*)d_in[1];
    const float* bng    = (const float*)d_in[2];
    const float* bnb    = (const float*)d_in[3];
    const float* bnm    = (const float*)d_in[4];
    const float* bnv    = (const float*)d_in[5];
    const float* fc1w   = (const float*)d_in[6];
    const float* fc1b   = (const float*)d_in[7];
    const float* fc2w   = (const float*)d_in[8];
    const float* fc2b   = (const float*)d_in[9];
    const float* dyw    = (const float*)d_in[10];
    const float* dyb    = (const float*)d_in[11];
    const float* g1     = (const float*)d_in[12];
    const float* b1     = (const float*)d_in[13];
    const float* m1     = (const float*)d_in[14];
    const float* v1     = (const float*)d_in[15];
    float* out = (float*)d_out;

    k1_conv1<<<dim3(P_/64, C2_/64, B_), 256>>>(x, conv1w, bng, bnb, bnm, bnv);
    k2_stats<<<B_*C2_, 256>>>();
    k3_attn<<<B_, 32>>>(fc1w, fc1b, fc2w, fc2b);
    k4_aggw<<<(B_*C2_*C2_*9/4)/256, 256>>>(dyw);
    k4_aggb<<<B_*C2_/256, 256>>>(dyb);
    k5_dyconv<<<dim3(25, C2_/32, B_), 256>>>(g1, b1, m1, v1, out);
}

// round 3
// speedup vs baseline: 1.1541x; 1.1541x over previous
#include <cuda_runtime.h>
#include <cuda_bf16.h>
#include <cstdint>
#include <cstddef>

// Problem constants
#define B_  16
#define C1_ 128
#define C2_ 256
#define KK_ 4
#define H_  80
#define W_  80
#define P_  (H_*W_)           // 6400
#define EPS_ 1e-5f

// Scratch (device globals; no allocation allowed)
__device__ float g_y[B_*C2_*P_];          // post conv1+bn+silu   (~104.9 MB)
__device__ float g_mu[B_*C2_];
__device__ float g_rstd[B_*C2_];
__device__ float g_attn[B_*KK_];
__device__ float g_aggwT[B_*C2_*9*C2_];   // per-sample weights [b][ci][q][o] (~37.7 MB)
__device__ float g_aggb[B_*C2_];

// ---------------------------------------------------------------------------
// K1: y = silu(bn(conv1x1(x)))   GEMM per-sample: Y[o,p] = sum_c W[o,c]X[c,p]
// ---------------------------------------------------------------------------
__global__ __launch_bounds__(256)
void k1_conv1(const float* __restrict__ x, const float* __restrict__ w,
              const float* __restrict__ bng, const float* __restrict__ bnb,
              const float* __restrict__ bnm, const float* __restrict__ bnv)
{
    __shared__ float As[32][68];   // [c][o], padded
    __shared__ float Bs[32][68];   // [c][p], padded

    const int b  = blockIdx.z;
    const int o0 = blockIdx.y * 64;
    const int p0 = blockIdx.x * 64;
    const int tid = threadIdx.x;
    const int tx = tid & 15, ty = tid >> 4;

    float acc[4][4];
#pragma unroll
    for (int j = 0; j < 4; ++j)
#pragma unroll
        for (int i = 0; i < 4; ++i) acc[j][i] = 0.f;

    for (int c0 = 0; c0 < C1_; c0 += 32) {
#pragma unroll
        for (int r = 0; r < 8; ++r) {
            int l = tid + 256*r;
            int o = l >> 5, c = l & 31;
            As[c][o] = w[(o0+o)*C1_ + c0 + c];
        }
#pragma unroll
        for (int r = 0; r < 2; ++r) {
            int l = tid + 256*r;
            int c = l >> 4, p4 = l & 15;
            float4 v = *(const float4*)(x + ((size_t)(b*C1_ + c0 + c))*P_ + p0 + p4*4);
            *(float4*)&Bs[c][p4*4] = v;
        }
        __syncthreads();
#pragma unroll
        for (int kk = 0; kk < 32; ++kk) {
            float4 av = *(const float4*)&As[kk][ty*4];
            float4 bv = *(const float4*)&Bs[kk][tx*4];
            float ar[4] = {av.x, av.y, av.z, av.w};
            float br[4] = {bv.x, bv.y, bv.z, bv.w};
#pragma unroll
            for (int j = 0; j < 4; ++j)
#pragma unroll
                for (int i = 0; i < 4; ++i) acc[j][i] += ar[j]*br[i];
        }
        __syncthreads();
    }

#pragma unroll
    for (int j = 0; j < 4; ++j) {
        int o = o0 + ty*4 + j;
        float s = bng[o] * rsqrtf(bnv[o] + EPS_);
        float t = bnb[o] - bnm[o]*s;
        float4 r;
        float vv;
        vv = acc[j][0]*s + t; r.x = vv / (1.f + expf(-vv));
        vv = acc[j][1]*s + t; r.y = vv / (1.f + expf(-vv));
        vv = acc[j][2]*s + t; r.z = vv / (1.f + expf(-vv));
        vv = acc[j][3]*s + t; r.w = vv / (1.f + expf(-vv));
        *(float4*)&g_y[((size_t)(b*C2_ + o))*P_ + p0 + tx*4] = r;
    }
}

// ---------------------------------------------------------------------------
// K2: per (b,c) mean / rstd (mean == GAP pooled)
// ---------------------------------------------------------------------------
__global__ __launch_bounds__(256)
void k2_stats()
{
    const int bc = blockIdx.x;
    const float* p = g_y + (size_t)bc * P_;
    float s = 0.f, s2 = 0.f;
    for (int i = threadIdx.x; i < P_; i += 256) {
        float v = p[i];
        s += v; s2 += v*v;
    }
    __shared__ float sh[8], sh2[8];
    const int lane = threadIdx.x & 31, wid = threadIdx.x >> 5;
#pragma unroll
    for (int off = 16; off; off >>= 1) {
        s  += __shfl_down_sync(0xffffffffu, s,  off);
        s2 += __shfl_down_sync(0xffffffffu, s2, off);
    }
    if (lane == 0) { sh[wid] = s; sh2[wid] = s2; }
    __syncthreads();
    if (threadIdx.x == 0) {
        float t = 0.f, t2 = 0.f;
#pragma unroll
        for (int i = 0; i < 8; ++i) { t += sh[i]; t2 += sh2[i]; }
        float mu  = t  * (1.f / P_);
        float var = t2 * (1.f / P_) - mu*mu;
        g_mu[bc]   = mu;
        g_rstd[bc] = rsqrtf(fmaxf(var, 0.f) + EPS_);
    }
}

// ---------------------------------------------------------------------------
// K3: attention (one warp per sample)
// ---------------------------------------------------------------------------
__global__ void k3_attn(const float* __restrict__ fc1w, const float* __restrict__ fc1b,
                        const float* __restrict__ fc2w, const float* __restrict__ fc2b)
{
    const int b = blockIdx.x, lane = threadIdx.x;
    float s0 = 0.f, s1 = 0.f, s2 = 0.f, s3 = 0.f;
    for (int c = lane; c < C2_; c += 32) {
        float pv = g_mu[b*C2_ + c];
        s0 += pv * fc1w[0*C2_ + c];
        s1 += pv * fc1w[1*C2_ + c];
        s2 += pv * fc1w[2*C2_ + c];
        s3 += pv * fc1w[3*C2_ + c];
    }
#pragma unroll
    for (int off = 16; off; off >>= 1) {
        s0 += __shfl_down_sync(0xffffffffu, s0, off);
        s1 += __shfl_down_sync(0xffffffffu, s1, off);
        s2 += __shfl_down_sync(0xffffffffu, s2, off);
        s3 += __shfl_down_sync(0xffffffffu, s3, off);
    }
    if (lane == 0) {
        float a[4];
        a[0] = fmaxf(s0 + fc1b[0], 0.f);
        a[1] = fmaxf(s1 + fc1b[1], 0.f);
        a[2] = fmaxf(s2 + fc1b[2], 0.f);
        a[3] = fmaxf(s3 + fc1b[3], 0.f);
        float l[4];
#pragma unroll
        for (int j = 0; j < 4; ++j)
            l[j] = a[0]*fc2w[j*4+0] + a[1]*fc2w[j*4+1] + a[2]*fc2w[j*4+2] + a[3]*fc2w[j*4+3] + fc2b[j];
        float m = fmaxf(fmaxf(l[0], l[1]), fmaxf(l[2], l[3]));
        float e[4], den = 0.f;
#pragma unroll
        for (int j = 0; j < 4; ++j) { e[j] = expf(l[j] - m); den += e[j]; }
        float inv = 1.f / den;
#pragma unroll
        for (int j = 0; j < 4; ++j) g_attn[b*4 + j] = e[j] * inv;
    }
}

// ---------------------------------------------------------------------------
// K4a: agg_w, written TRANSPOSED: g_aggwT[b][ci][q][o]
// block = (b, o-group of 32, ci-group of 8); smem transpose for coalescing
// ---------------------------------------------------------------------------
__global__ __launch_bounds__(256)
void k4_aggw(const float* __restrict__ dyw)
{
    __shared__ float t[72][33];
    const int b   = blockIdx.z;
    const int o0  = blockIdx.y * 32;
    const int ci0 = blockIdx.x * 8;
    const int tid = threadIdx.x;

    const float a0 = g_attn[b*4+0], a1 = g_attn[b*4+1];
    const float a2 = g_attn[b*4+2], a3 = g_attn[b*4+3];
    const size_t kstride = (size_t)C2_*C2_*9;

    // read coalesced from dyw [k][o][ci][q]; 2304 elems
#pragma unroll
    for (int r = 0; r < 9; ++r) {
        int l = tid + 256*r;
        int o  = l / 72;
        int rm = l - o*72;
        int ci = rm / 9;
        int q  = rm - ci*9;
        size_t base = ((size_t)(o0+o)*C2_ + ci0+ci)*9 + q;
        float v = a0*dyw[base] + a1*dyw[base + kstride]
                + a2*dyw[base + 2*kstride] + a3*dyw[base + 3*kstride];
        t[ci*9+q][o] = v;
    }
    __syncthreads();
    // write coalesced to g_aggwT[b][ci][q][o]
#pragma unroll
    for (int r = 0; r < 9; ++r) {
        int l = tid + 256*r;
        int ciq = l >> 5;          // 0..71
        int o   = l & 31;
        int ci = ciq / 9, q = ciq - ci*9;
        g_aggwT[(((size_t)b*C2_ + ci0+ci)*9 + q)*C2_ + o0 + o] = t[ciq][o];
    }
}

// K4b: agg_b[b,o]
__global__ void k4_aggb(const float* __restrict__ dyb)
{
    int idx = blockIdx.x*256 + threadIdx.x;   // B_*C2_ = 4096
    int b = idx >> 8, o = idx & 255;
    float v = 0.f;
#pragma unroll
    for (int k = 0; k < 4; ++k) v += g_attn[b*4+k] * dyb[k*C2_ + o];
    g_aggb[idx] = v;
}

// ---------------------------------------------------------------------------
// K5 v2: per-sample 3x3 conv, InstanceNorm fused into patch load, + bias + bn1
// Block: (b, 64 out-ch, 16x16 px). Thread: 2x2 px quad x 16 channels.
// Per ci: 576 FFMA vs ~52 LDS per thread -> FFMA-pipe bound.
// ---------------------------------------------------------------------------
__global__ __launch_bounds__(256)
void k5_dyconv(const float* __restrict__ g1, const float* __restrict__ b1,
               const float* __restrict__ m1, const float* __restrict__ v1,
               float* __restrict__ out)
{
    __shared__ float patch[18*18];
    __shared__ float wsm[9][64];       // [q][o-local]

    const int b    = blockIdx.z;
    const int o0   = blockIdx.y * 64;
    const int tile = blockIdx.x;       // 0..24
    const int h0 = (tile / 5) * 16;
    const int w0 = (tile % 5) * 16;
    const int tid = threadIdx.x;
    const int cg   = tid & 3;          // channel group (16 ch)
    const int quad = tid >> 2;         // 0..63
    const int qx = quad & 7, qy = quad >> 3;

    float4 acc[4][4];                  // [pixel: (0,0)(0,1)(1,0)(1,1)][j]
#pragma unroll
    for (int p = 0; p < 4; ++p)
#pragma unroll
        for (int j = 0; j < 4; ++j) acc[p][j] = make_float4(0.f,0.f,0.f,0.f);

    const float* yb  = g_y + (size_t)b*C2_*P_;
    const float* wTb = g_aggwT + (size_t)b*C2_*9*C2_;
    const int r0 = 2*qy, c0 = 2*qx;

    for (int ci = 0; ci < C2_; ++ci) {
        const float cmu = __ldg(&g_mu[b*C2_ + ci]);
        const float cr  = __ldg(&g_rstd[b*C2_ + ci]);
        const float* yc = yb + (size_t)ci * P_;
        // 18x18 normalized patch with zero halo (324 elems)
        for (int idx = tid; idx < 324; idx += 256) {
            int r = idx / 18, c = idx - r*18;
            int gh = h0 + r - 1, gw = w0 + c - 1;
            float v = 0.f;
            if (gh >= 0 && gh < H_ && gw >= 0 && gw < W_)
                v = (yc[gh*W_ + gw] - cmu) * cr;
            patch[idx] = v;
        }
        // weights: 9*64 = 576 contiguous floats = 144 float4
        if (tid < 144) {
            int q = tid >> 4, jj = tid & 15;
            float4 wv = *(const float4*)(wTb + ((size_t)ci*9 + q)*C2_ + o0 + jj*4);
            *(float4*)&wsm[q][jj*4] = wv;
        }
        __syncthreads();

        // preload 4x4 patch window into registers (float2 loads, 8B-aligned)
        float pv[4][4];
#pragma unroll
        for (int dy = 0; dy < 4; ++dy) {
            float2 a = *(const float2*)&patch[(r0+dy)*18 + c0];
            float2 bb = *(const float2*)&patch[(r0+dy)*18 + c0 + 2];
            pv[dy][0] = a.x; pv[dy][1] = a.y; pv[dy][2] = bb.x; pv[dy][3] = bb.y;
        }

#pragma unroll
        for (int q = 0; q < 9; ++q) {
            const int dy = q / 3, dx = q - dy*3;
            const float* wq = &wsm[q][cg*16];
            float4 w0v = *(const float4*)(wq);
            float4 w1v = *(const float4*)(wq + 4);
            float4 w2v = *(const float4*)(wq + 8);
            float4 w3v = *(const float4*)(wq + 12);
            const float pA = pv[dy][dx],   pB = pv[dy][dx+1];
            const float pC = pv[dy+1][dx], pD = pv[dy+1][dx+1];
#define FMA4(A, P, W) A.x += (P)*(W).x; A.y += (P)*(W).y; A.z += (P)*(W).z; A.w += (P)*(W).w;
            FMA4(acc[0][0], pA, w0v) FMA4(acc[0][1], pA, w1v) FMA4(acc[0][2], pA, w2v) FMA4(acc[0][3], pA, w3v)
            FMA4(acc[1][0], pB, w0v) FMA4(acc[1][1], pB, w1v) FMA4(acc[1][2], pB, w2v) FMA4(acc[1][3], pB, w3v)
            FMA4(acc[2][0], pC, w0v) FMA4(acc[2][1], pC, w1v) FMA4(acc[2][2], pC, w2v) FMA4(acc[2][3], pC, w3v)
            FMA4(acc[3][0], pD, w0v) FMA4(acc[3][1], pD, w1v) FMA4(acc[3][2], pD, w2v) FMA4(acc[3][3], pD, w3v)
#undef FMA4
        }
        __syncthreads();
    }

    // Epilogue: res = acc*s + ((aggb - m1)*s + b1), s = g1*rsqrt(v1+eps)
    const int h = h0 + 2*qy;
    const int w = w0 + 2*qx;
#pragma unroll
    for (int j = 0; j < 4; ++j) {
        const int ob = o0 + cg*16 + j*4;
        float4 gv = *(const float4*)(g1 + ob);
        float4 vv = *(const float4*)(v1 + ob);
        float4 mv = *(const float4*)(m1 + ob);
        float4 bv = *(const float4*)(b1 + ob);
        float4 av = *(const float4*)(&g_aggb[b*C2_ + ob]);
        float4 s, off;
        s.x = gv.x*rsqrtf(vv.x+EPS_); off.x = (av.x - mv.x)*s.x + bv.x;
        s.y = gv.y*rsqrtf(vv.y+EPS_); off.y = (av.y - mv.y)*s.y + bv.y;
        s.z = gv.z*rsqrtf(vv.z+EPS_); off.z = (av.z - mv.z)*s.z + bv.z;
        s.w = gv.w*rsqrtf(vv.w+EPS_); off.w = (av.w - mv.w)*s.w + bv.w;
#define EPI(COMP, CIDX) { \
        float* po = out + ((size_t)(b*C2_ + ob + CIDX))*P_ + h*W_ + w; \
        float2 r0v, r1v; \
        r0v.x = acc[0][j].COMP*s.COMP + off.COMP; \
        r0v.y = acc[1][j].COMP*s.COMP + off.COMP; \
        r1v.x = acc[2][j].COMP*s.COMP + off.COMP; \
        r1v.y = acc[3][j].COMP*s.COMP + off.COMP; \
        *(float2*)po = r0v; *(float2*)(po + W_) = r1v; }
        EPI(x, 0) EPI(y, 1) EPI(z, 2) EPI(w, 3)
#undef EPI
    }
}

// ---------------------------------------------------------------------------
extern "C" void kernel_launch(void* const* d_in, const int* in_sizes, int n_in,
                              void* d_out, int out_size)
{
    const float* x      = (const float*)d_in[0];
    const float* conv1w = (const float*)d_in[1];
    const float* bng    = (const float*)d_in[2];
    const float* bnb    = (const float*)d_in[3];
    const float* bnm    = (const float*)d_in[4];
    const float* bnv    = (const float*)d_in[5];
    const float* fc1w   = (const float*)d_in[6];
    const float* fc1b   = (const float*)d_in[7];
    const float* fc2w   = (const float*)d_in[8];
    const float* fc2b   = (const float*)d_in[9];
    const float* dyw    = (const float*)d_in[10];
    const float* dyb    = (const float*)d_in[11];
    const float* g1     = (const float*)d_in[12];
    const float* b1     = (const float*)d_in[13];
    const float* m1     = (const float*)d_in[14];
    const float* v1     = (const float*)d_in[15];
    float* out = (float*)d_out;

    k1_conv1<<<dim3(P_/64, C2_/64, B_), 256>>>(x, conv1w, bng, bnb, bnm, bnv);
    k2_stats<<<B_*C2_, 256>>>();
    k3_attn<<<B_, 32>>>(fc1w, fc1b, fc2w, fc2b);
    k4_aggw<<<dim3(C2_/8, C2_/32, B_), 256>>>(dyw);
    k4_aggb<<<B_*C2_/256, 256>>>(dyb);
    k5_dyconv<<<dim3(25, C2_/64, B_), 256>>>(g1, b1, m1, v1, out);
}

// round 4
// speedup vs baseline: 3.7201x; 3.2234x over previous
#include <cuda_runtime.h>
#include <cuda_bf16.h>
#include <cstdint>
#include <cstddef>

// Problem constants
#define B_  16
#define C1_ 128
#define C2_ 256
#define H_  80
#define W_  80
#define P_  (H_*W_)           // 6400
#define EPS_ 1e-5f

#define KCH 88                // padded k per ci-chunk (9 taps*8ci=72 -> +dummy tap -> 80 -> pad 88)
#define NCH 32                // ci-chunks (256/8)

// Scratch (device globals)
__device__ float g_y[B_*C2_*P_];
__device__ float g_mu[B_*C2_];
__device__ float g_rstd[B_*C2_];
__device__ float g_attn[B_*4];
__device__ float g_aggb[B_*C2_];
// MMA weights: [b][og2][ch32][half2][o128][KCH] bf16 (~46 MB)
__device__ __align__(16) __nv_bfloat16 g_wm[(size_t)B_*2*NCH*2*128*KCH];
// MMA input:   [b][pix6400][half2][ci256] bf16 (~105 MB)
__device__ __align__(16) __nv_bfloat16 g_ym[(size_t)B_*P_*2*C2_];

// ---------------------------------------------------------------------------
// K1: y = silu(bn(conv1x1(x)))
// ---------------------------------------------------------------------------
__global__ __launch_bounds__(256)
void k1_conv1(const float* __restrict__ x, const float* __restrict__ w,
              const float* __restrict__ bng, const float* __restrict__ bnb,
              const float* __restrict__ bnm, const float* __restrict__ bnv)
{
    __shared__ float As[32][68];
    __shared__ float Bs[32][68];

    const int b  = blockIdx.z;
    const int o0 = blockIdx.y * 64;
    const int p0 = blockIdx.x * 64;
    const int tid = threadIdx.x;
    const int tx = tid & 15, ty = tid >> 4;

    float acc[4][4];
#pragma unroll
    for (int j = 0; j < 4; ++j)
#pragma unroll
        for (int i = 0; i < 4; ++i) acc[j][i] = 0.f;

    for (int c0 = 0; c0 < C1_; c0 += 32) {
#pragma unroll
        for (int r = 0; r < 8; ++r) {
            int l = tid + 256*r;
            int o = l >> 5, c = l & 31;
            As[c][o] = w[(o0+o)*C1_ + c0 + c];
        }
#pragma unroll
        for (int r = 0; r < 2; ++r) {
            int l = tid + 256*r;
            int c = l >> 4, p4 = l & 15;
            float4 v = *(const float4*)(x + ((size_t)(b*C1_ + c0 + c))*P_ + p0 + p4*4);
            *(float4*)&Bs[c][p4*4] = v;
        }
        __syncthreads();
#pragma unroll
        for (int kk = 0; kk < 32; ++kk) {
            float4 av = *(const float4*)&As[kk][ty*4];
            float4 bv = *(const float4*)&Bs[kk][tx*4];
            float ar[4] = {av.x, av.y, av.z, av.w};
            float br[4] = {bv.x, bv.y, bv.z, bv.w};
#pragma unroll
            for (int j = 0; j < 4; ++j)
#pragma unroll
                for (int i = 0; i < 4; ++i) acc[j][i] += ar[j]*br[i];
        }
        __syncthreads();
    }

#pragma unroll
    for (int j = 0; j < 4; ++j) {
        int o = o0 + ty*4 + j;
        float s = bng[o] * rsqrtf(bnv[o] + EPS_);
        float t = bnb[o] - bnm[o]*s;
        float4 r;
        float vv;
        vv = acc[j][0]*s + t; r.x = vv / (1.f + expf(-vv));
        vv = acc[j][1]*s + t; r.y = vv / (1.f + expf(-vv));
        vv = acc[j][2]*s + t; r.z = vv / (1.f + expf(-vv));
        vv = acc[j][3]*s + t; r.w = vv / (1.f + expf(-vv));
        *(float4*)&g_y[((size_t)(b*C2_ + o))*P_ + p0 + tx*4] = r;
    }
}

// ---------------------------------------------------------------------------
// K2: per (b,c) mean / rstd
// ---------------------------------------------------------------------------
__global__ __launch_bounds__(256)
void k2_stats()
{
    const int bc = blockIdx.x;
    const float* p = g_y + (size_t)bc * P_;
    float s = 0.f, s2 = 0.f;
    for (int i = threadIdx.x; i < P_; i += 256) {
        float v = p[i];
        s += v; s2 += v*v;
    }
    __shared__ float sh[8], sh2[8];
    const int lane = threadIdx.x & 31, wid = threadIdx.x >> 5;
#pragma unroll
    for (int off = 16; off; off >>= 1) {
        s  += __shfl_down_sync(0xffffffffu, s,  off);
        s2 += __shfl_down_sync(0xffffffffu, s2, off);
    }
    if (lane == 0) { sh[wid] = s; sh2[wid] = s2; }
    __syncthreads();
    if (threadIdx.x == 0) {
        float t = 0.f, t2 = 0.f;
#pragma unroll
        for (int i = 0; i < 8; ++i) { t += sh[i]; t2 += sh2[i]; }
        float mu  = t  * (1.f / P_);
        float var = t2 * (1.f / P_) - mu*mu;
        g_mu[bc]   = mu;
        g_rstd[bc] = rsqrtf(fmaxf(var, 0.f) + EPS_);
    }
}

// ---------------------------------------------------------------------------
// K2b: yn split hi/lo bf16, transposed to [b][pix][half][ci]
// block: (pixg25, cig8, b16); tile 32ci x 256px
// ---------------------------------------------------------------------------
__global__ __launch_bounds__(256)
void k2b_split()
{
    __shared__ __nv_bfloat16 th[32][258];
    __shared__ __nv_bfloat16 tl[32][258];
    const int b = blockIdx.z, ci0 = blockIdx.y*32, p0 = blockIdx.x*256;
    const int tid = threadIdx.x;

#pragma unroll
    for (int it = 0; it < 8; ++it) {
        int r  = it*4 + (tid>>6);
        int px = (tid&63)*4;
        int ci = ci0 + r;
        float mu = __ldg(&g_mu[b*C2_+ci]), rs = __ldg(&g_rstd[b*C2_+ci]);
        float4 v = *(const float4*)&g_y[((size_t)(b*C2_+ci))*P_ + p0 + px];
        float vs[4] = {(v.x-mu)*rs, (v.y-mu)*rs, (v.z-mu)*rs, (v.w-mu)*rs};
#pragma unroll
        for (int j = 0; j < 4; ++j) {
            __nv_bfloat16 vh = __float2bfloat16(vs[j]);
            th[r][px+j] = vh;
            tl[r][px+j] = __float2bfloat16(vs[j] - __bfloat162float(vh));
        }
    }
    __syncthreads();
#pragma unroll
    for (int it = 0; it < 16; ++it) {
        int px = it*16 + (tid>>4);
        int cq = tid & 15;
        __nv_bfloat162 hp, lp;
        hp.x = th[cq*2][px]; hp.y = th[cq*2+1][px];
        lp.x = tl[cq*2][px]; lp.y = tl[cq*2+1][px];
        size_t base = ((size_t)b*P_ + p0 + px)*2*(size_t)C2_;
        *(__nv_bfloat162*)&g_ym[base + ci0 + cq*2]        = hp;
        *(__nv_bfloat162*)&g_ym[base + C2_ + ci0 + cq*2]  = lp;
    }
}

// ---------------------------------------------------------------------------
// K3: attention (one warp per sample)
// ---------------------------------------------------------------------------
__global__ void k3_attn(const float* __restrict__ fc1w, const float* __restrict__ fc1b,
                        const float* __restrict__ fc2w, const float* __restrict__ fc2b)
{
    const int b = blockIdx.x, lane = threadIdx.x;
    float s0 = 0.f, s1 = 0.f, s2 = 0.f, s3 = 0.f;
    for (int c = lane; c < C2_; c += 32) {
        float pv = g_mu[b*C2_ + c];
        s0 += pv * fc1w[0*C2_ + c];
        s1 += pv * fc1w[1*C2_ + c];
        s2 += pv * fc1w[2*C2_ + c];
        s3 += pv * fc1w[3*C2_ + c];
    }
#pragma unroll
    for (int off = 16; off; off >>= 1) {
        s0 += __shfl_down_sync(0xffffffffu, s0, off);
        s1 += __shfl_down_sync(0xffffffffu, s1, off);
        s2 += __shfl_down_sync(0xffffffffu, s2, off);
        s3 += __shfl_down_sync(0xffffffffu, s3, off);
    }
    if (lane == 0) {
        float a[4];
        a[0] = fmaxf(s0 + fc1b[0], 0.f);
        a[1] = fmaxf(s1 + fc1b[1], 0.f);
        a[2] = fmaxf(s2 + fc1b[2], 0.f);
        a[3] = fmaxf(s3 + fc1b[3], 0.f);
        float l[4];
#pragma unroll
        for (int j = 0; j < 4; ++j)
            l[j] = a[0]*fc2w[j*4+0] + a[1]*fc2w[j*4+1] + a[2]*fc2w[j*4+2] + a[3]*fc2w[j*4+3] + fc2b[j];
        float m = fmaxf(fmaxf(l[0], l[1]), fmaxf(l[2], l[3]));
        float e[4], den = 0.f;
#pragma unroll
        for (int j = 0; j < 4; ++j) { e[j] = expf(l[j] - m); den += e[j]; }
        float inv = 1.f / den;
#pragma unroll
        for (int j = 0; j < 4; ++j) g_attn[b*4 + j] = e[j] * inv;
    }
}

// ---------------------------------------------------------------------------
// K4: aggregate weights -> bf16 hi/lo in MMA-ready layout
// thread per (b,og,ch,o,k); k = q*8+ci_sub, k>=72 -> zero
// ---------------------------------------------------------------------------
__global__ __launch_bounds__(256)
void k4_aggw(const float* __restrict__ dyw)
{
    size_t idx = (size_t)blockIdx.x*256 + threadIdx.x;   // 16*2*32*128*88
    int k = (int)(idx % KCH);
    size_t r = idx / KCH;
    int o  = (int)(r % 128); r /= 128;
    int ch = (int)(r % NCH); r /= NCH;
    int og = (int)(r % 2);
    int b  = (int)(r / 2);

    float v = 0.f;
    if (k < 72) {
        int q  = k >> 3;
        int ci = ch*8 + (k & 7);
        int oi = og*128 + o;
        const size_t ks = (size_t)C2_*C2_*9;
        size_t base = ((size_t)oi*C2_ + ci)*9 + q;
        v = g_attn[b*4+0]*__ldg(&dyw[base])
          + g_attn[b*4+1]*__ldg(&dyw[base + ks])
          + g_attn[b*4+2]*__ldg(&dyw[base + 2*ks])
          + g_attn[b*4+3]*__ldg(&dyw[base + 3*ks]);
    }
    __nv_bfloat16 vh = __float2bfloat16(v);
    float vl = v - __bfloat162float(vh);
    size_t outb = ((((size_t)b*2 + og)*NCH + ch)*2)*(size_t)(128*KCH) + (size_t)o*KCH + k;
    g_wm[outb] = vh;
    g_wm[outb + 128*KCH] = __float2bfloat16(vl);
}

// K4b: agg_b[b,o]
__global__ void k4_aggb(const float* __restrict__ dyb)
{
    int idx = blockIdx.x*256 + threadIdx.x;   // 4096
    int b = idx >> 8, o = idx & 255;
    float v = 0.f;
#pragma unroll
    for (int k = 0; k < 4; ++k) v += g_attn[b*4+k] * dyb[k*C2_ + o];
    g_aggb[idx] = v;
}

// ---------------------------------------------------------------------------
// K5: tensor-core implicit-GEMM 3x3 conv (3-pass bf16 split), + bias + bn1
// Block: (b, 128 o, 64 px = 4x16). 8 warps = 4M x 2N. mma.m16n8k16.bf16.
// ---------------------------------------------------------------------------
__device__ __forceinline__ void mma16816(float* d, const uint32_t* a, const uint32_t* bb)
{
    asm volatile(
        "mma.sync.aligned.m16n8k16.row.col.f32.bf16.bf16.f32 "
        "{%0,%1,%2,%3}, {%4,%5,%6,%7}, {%8,%9}, {%0,%1,%2,%3};"
        : "+f"(d[0]), "+f"(d[1]), "+f"(d[2]), "+f"(d[3])
        : "r"(a[0]), "r"(a[1]), "r"(a[2]), "r"(a[3]), "r"(bb[0]), "r"(bb[1]));
}

__global__ __launch_bounds__(256)
void k5_mma(const float* __restrict__ g1, const float* __restrict__ b1,
            const float* __restrict__ m1, const float* __restrict__ v1,
            float* __restrict__ out)
{
    __shared__ __align__(16) __nv_bfloat16 As[2][128*KCH];   // [half][o*KCH+k]
    __shared__ __align__(16) __nv_bfloat16 Bs[2][108*8];     // [half][pix*8+ci]

    const int b    = blockIdx.z;
    const int og   = blockIdx.y;
    const int tile = blockIdx.x;                 // 0..99
    const int h0 = (tile/5)*4, w0 = (tile%5)*16;
    const int tid  = threadIdx.x;
    const int lane = tid & 31, warp = tid >> 5;
    const int warp_m = warp & 3, warp_n = warp >> 2;

    float acc[2][4][4];
#pragma unroll
    for (int mr = 0; mr < 2; ++mr)
#pragma unroll
        for (int nr = 0; nr < 4; ++nr)
#pragma unroll
            for (int j = 0; j < 4; ++j) acc[mr][nr][j] = 0.f;

    const __nv_bfloat16* wsrc = g_wm + (((size_t)b*2 + og)*NCH)*2*(size_t)(128*KCH);

    // B staging setup (threads 0..215: px = tid>>1, half = tid&1)
    const int st_px = tid >> 1, st_half = tid & 1;
    const int st_r = st_px/18, st_c = st_px - st_r*18;
    const int gh = h0 + st_r - 1, gw = w0 + st_c - 1;
    const bool st_ok = (tid < 216) && gh >= 0 && gh < H_ && gw >= 0 && gw < W_;
    const int ghc = max(0, min(H_-1, gh)), gwc = max(0, min(W_-1, gw));
    const size_t st_src0 = (((size_t)b*P_ + ghc*W_ + gwc)*2 + st_half)*(size_t)C2_;

    // shift tables (q0 = 2s, q1 = 2s+1; s=4 -> q1=9 dummy)
    const int DY0[5] = {0,0,1,2,2}, DX0[5] = {0,2,1,0,2};
    const int DY1[5] = {0,1,1,2,0}, DX1[5] = {1,0,2,1,0};

    for (int ch = 0; ch < NCH; ++ch) {
        // stage A: 45056 B contiguous copy
        const int4* asrc = (const int4*)(wsrc + (size_t)ch*2*128*KCH);
        int4* adst = (int4*)&As[0][0];
#pragma unroll
        for (int i = 0; i < 11; ++i)
            adst[tid + 256*i] = asrc[tid + 256*i];
        // stage B halo tile
        if (tid < 216) {
            int4 vv = make_int4(0,0,0,0);
            if (st_ok) vv = *(const int4*)(g_ym + st_src0 + ch*8);
            *(int4*)&Bs[st_half][st_px*8] = vv;
        }
        __syncthreads();

#pragma unroll
        for (int s = 0; s < 5; ++s) {
            // A fragments
            uint32_t ah[2][4], al[2][4];
            const int kb = 16*s + 2*(lane&3);
#pragma unroll
            for (int mr = 0; mr < 2; ++mr) {
                int o = warp_m*32 + mr*16 + (lane>>2);
                const uint32_t* ph  = (const uint32_t*)&As[0][o*KCH + kb];
                const uint32_t* ph8 = (const uint32_t*)&As[0][(o+8)*KCH + kb];
                const uint32_t* pl  = (const uint32_t*)&As[1][o*KCH + kb];
                const uint32_t* pl8 = (const uint32_t*)&As[1][(o+8)*KCH + kb];
                ah[mr][0] = ph[0];  ah[mr][1] = ph8[0];  ah[mr][2] = ph[4];  ah[mr][3] = ph8[4];
                al[mr][0] = pl[0];  al[mr][1] = pl8[0];  al[mr][2] = pl[4];  al[mr][3] = pl8[4];
            }
            // B fragments
            const int dy0 = DY0[s], dx0 = DX0[s], dy1 = DY1[s], dx1 = DX1[s];
            uint32_t bh[4][2], bl[4][2];
#pragma unroll
            for (int nr = 0; nr < 4; ++nr) {
                int pr = warp_n*2 + (nr>>1);
                int pc = (nr&1)*8 + (lane>>2);
                int i0 = ((pr+dy0)*18 + pc+dx0)*8 + 2*(lane&3);
                int i1 = ((pr+dy1)*18 + pc+dx1)*8 + 2*(lane&3);
                bh[nr][0] = *(const uint32_t*)&Bs[0][i0];
                bh[nr][1] = *(const uint32_t*)&Bs[0][i1];
                bl[nr][0] = *(const uint32_t*)&Bs[1][i0];
                bl[nr][1] = *(const uint32_t*)&Bs[1][i1];
            }
            // 3-pass MMA: hi*hi + hi*lo + lo*hi
#pragma unroll
            for (int mr = 0; mr < 2; ++mr)
#pragma unroll
                for (int nr = 0; nr < 4; ++nr) {
                    mma16816(acc[mr][nr], ah[mr], bh[nr]);
                    mma16816(acc[mr][nr], ah[mr], bl[nr]);
                    mma16816(acc[mr][nr], al[mr], bh[nr]);
                }
        }
        __syncthreads();
    }

    // Epilogue: res = acc*s + ((aggb - m1)*s + b1)
    const int obase = og*128 + warp_m*32;
#pragma unroll
    for (int mr = 0; mr < 2; ++mr) {
        const int o_a = obase + mr*16 + (lane>>2);
        const int o_b = o_a + 8;
        float sA = __ldg(&g1[o_a]) * rsqrtf(__ldg(&v1[o_a]) + EPS_);
        float offA = (__ldg(&g_aggb[b*C2_+o_a]) - __ldg(&m1[o_a]))*sA + __ldg(&b1[o_a]);
        float sB = __ldg(&g1[o_b]) * rsqrtf(__ldg(&v1[o_b]) + EPS_);
        float offB = (__ldg(&g_aggb[b*C2_+o_b]) - __ldg(&m1[o_b]))*sB + __ldg(&b1[o_b]);
#pragma unroll
        for (int nr = 0; nr < 4; ++nr) {
            int pr = warp_n*2 + (nr>>1);
            int pc = (nr&1)*8 + 2*(lane&3);
            size_t po = (size_t)(h0+pr)*W_ + w0 + pc;
            float2 vA, vB;
            vA.x = acc[mr][nr][0]*sA + offA;  vA.y = acc[mr][nr][1]*sA + offA;
            vB.x = acc[mr][nr][2]*sB + offB;  vB.y = acc[mr][nr][3]*sB + offB;
            *(float2*)&out[((size_t)(b*C2_+o_a))*P_ + po] = vA;
            *(float2*)&out[((size_t)(b*C2_+o_b))*P_ + po] = vB;
        }
    }
}

// ---------------------------------------------------------------------------
extern "C" void kernel_launch(void* const* d_in, const int* in_sizes, int n_in,
                              void* d_out, int out_size)
{
    const float* x      = (const float*)d_in[0];
    const float* conv1w = (const float*)d_in[1];
    const float* bng    = (const float*)d_in[2];
    const float* bnb    = (const float*)d_in[3];
    const float* bnm    = (const float*)d_in[4];
    const float* bnv    = (const float*)d_in[5];
    const float* fc1w   = (const float*)d_in[6];
    const float* fc1b   = (const float*)d_in[7];
    const float* fc2w   = (const float*)d_in[8];
    const float* fc2b   = (const float*)d_in[9];
    const float* dyw    = (const float*)d_in[10];
    const float* dyb    = (const float*)d_in[11];
    const float* g1     = (const float*)d_in[12];
    const float* b1     = (const float*)d_in[13];
    const float* m1     = (const float*)d_in[14];
    const float* v1     = (const float*)d_in[15];
    float* out = (float*)d_out;

    k1_conv1<<<dim3(P_/64, C2_/64, B_), 256>>>(x, conv1w, bng, bnb, bnm, bnv);
    k2_stats<<<B_*C2_, 256>>>();
    k2b_split<<<dim3(25, 8, B_), 256>>>();
    k3_attn<<<B_, 32>>>(fc1w, fc1b, fc2w, fc2b);
    k4_aggw<<<(int)(((size_t)B_*2*NCH*128*KCH)/256), 256>>>(dyw);
    k4_aggb<<<B_*C2_/256, 256>>>(dyb);
    k5_mma<<<dim3(100, 2, B_), 256>>>(g1, b1, m1, v1, out);
}

// round 6
// speedup vs baseline: 4.8761x; 1.3107x over previous
#include <cuda_runtime.h>
#include <cuda_fp16.h>
#include <cstdint>
#include <cstddef>

// Problem constants
#define B_  16
#define C1_ 128
#define C2_ 256
#define H_  80
#define W_  80
#define P_  (H_*W_)           // 6400
#define EPS_ 1e-5f

#define KCH 88                // padded k per ci-chunk (9 taps*8ci=72 -> +dummy tap -> 80 -> pad 88)
#define NCH 32                // ci-chunks (256/8)

// Scratch (device globals)
__device__ float g_ps [B_*C2_*128];       // per-(b,o) partial sums over 100 px-tiles
__device__ float g_ps2[B_*C2_*128];
__device__ float g_mu[B_*C2_];
__device__ float g_rstd[B_*C2_];
__device__ float g_mr[B_*C2_];            // mu*rstd
__device__ float g_attn[B_*4];
__device__ float g_aggb[B_*C2_];
__device__ float g_cq [B_*C2_*9];         // Cq[b,o,q] = sum_ci w_agg*mu*rstd
__device__ float g_cqt[B_*C2_];           // sum_q Cq
// MMA weights (rstd-folded, fp16 hi/lo): [b][og2][ch32][half2][o128][KCH] (~46 MB)
__device__ __align__(16) __half g_wm[(size_t)B_*2*NCH*2*128*KCH];
// MMA input y (fp16, single): [b][pix6400][ci256] (~52 MB)
__device__ __align__(16) __half g_ym[(size_t)B_*P_*C2_];

// ---------------------------------------------------------------------------
// K1: y = silu(bn(conv1x1(x)))  -> fp16 transposed write to g_ym
//     + deterministic per-block partial sums for InstanceNorm stats
// ---------------------------------------------------------------------------
__global__ __launch_bounds__(256)
void k1_conv1(const float* __restrict__ x, const float* __restrict__ w,
              const float* __restrict__ bng, const float* __restrict__ bnb,
              const float* __restrict__ bnm, const float* __restrict__ bnv)
{
    __shared__ float As[32][68];
    __shared__ float Bs[32][68];
    __shared__ __half shm[64][72];      // [px][o], padded row (144B) vs conflicts

    const int b  = blockIdx.z;
    const int o0 = blockIdx.y * 64;
    const int p0 = blockIdx.x * 64;
    const int tid = threadIdx.x;
    const int tx = tid & 15, ty = tid >> 4;

    float acc[4][4];
#pragma unroll
    for (int j = 0; j < 4; ++j)
#pragma unroll
        for (int i = 0; i < 4; ++i) acc[j][i] = 0.f;

    for (int c0 = 0; c0 < C1_; c0 += 32) {
#pragma unroll
        for (int r = 0; r < 8; ++r) {
            int l = tid + 256*r;
            int o = l >> 5, c = l & 31;
            As[c][o] = w[(o0+o)*C1_ + c0 + c];
        }
#pragma unroll
        for (int r = 0; r < 2; ++r) {
            int l = tid + 256*r;
            int c = l >> 4, p4 = l & 15;
            float4 v = *(const float4*)(x + ((size_t)(b*C1_ + c0 + c))*P_ + p0 + p4*4);
            *(float4*)&Bs[c][p4*4] = v;
        }
        __syncthreads();
#pragma unroll
        for (int kk = 0; kk < 32; ++kk) {
            float4 av = *(const float4*)&As[kk][ty*4];
            float4 bv = *(const float4*)&Bs[kk][tx*4];
            float ar[4] = {av.x, av.y, av.z, av.w};
            float br[4] = {bv.x, bv.y, bv.z, bv.w};
#pragma unroll
            for (int j = 0; j < 4; ++j)
#pragma unroll
                for (int i = 0; i < 4; ++i) acc[j][i] += ar[j]*br[i];
        }
        __syncthreads();
    }

    // bn + silu; stash fp16 in smem; accumulate per-o partial sums
    float ps[4], ps2[4];
#pragma unroll
    for (int j = 0; j < 4; ++j) {
        int o = o0 + ty*4 + j;
        float s = bng[o] * rsqrtf(bnv[o] + EPS_);
        float t = bnb[o] - bnm[o]*s;
        ps[j] = 0.f; ps2[j] = 0.f;
#pragma unroll
        for (int i = 0; i < 4; ++i) {
            float vv = acc[j][i]*s + t;
            vv = vv / (1.f + expf(-vv));
            ps[j]  += vv;
            ps2[j] += vv*vv;
            shm[tx*4+i][ty*4+j] = __float2half_rn(vv);
        }
    }
#pragma unroll
    for (int off = 1; off <= 8; off <<= 1) {
#pragma unroll
        for (int j = 0; j < 4; ++j) {
            ps[j]  += __shfl_xor_sync(0xffffffffu, ps[j],  off);
            ps2[j] += __shfl_xor_sync(0xffffffffu, ps2[j], off);
        }
    }
    if (tx == 0) {
#pragma unroll
        for (int j = 0; j < 4; ++j) {
            int o = o0 + ty*4 + j;
            g_ps [(b*C2_+o)*128 + blockIdx.x] = ps[j];
            g_ps2[(b*C2_+o)*128 + blockIdx.x] = ps2[j];
        }
    }
    __syncthreads();
    // coalesced transposed write: g_ym[b][px][ci]
#pragma unroll
    for (int r = 0; r < 2; ++r) {
        int l = tid + 256*r;
        int px = l >> 3, seg = l & 7;
        *(int4*)(g_ym + ((size_t)b*P_ + p0 + px)*C2_ + o0 + seg*8) =
            *(const int4*)&shm[px][seg*8];
    }
}

// ---------------------------------------------------------------------------
// K2: finalize stats: mu, rstd, mu*rstd   (4096 threads)
// ---------------------------------------------------------------------------
__global__ void k2_fin()
{
    int idx = blockIdx.x*256 + threadIdx.x;   // b*C2 + o
    float s = 0.f, s2 = 0.f;
    for (int t = 0; t < 100; ++t) {
        s  += g_ps [idx*128 + t];
        s2 += g_ps2[idx*128 + t];
    }
    float mu  = s  * (1.f / P_);
    float var = s2 * (1.f / P_) - mu*mu;
    float rs  = rsqrtf(fmaxf(var, 0.f) + EPS_);
    g_mu[idx]   = mu;
    g_rstd[idx] = rs;
    g_mr[idx]   = mu * rs;
}

// ---------------------------------------------------------------------------
// K3: attention (one warp per sample)
// ---------------------------------------------------------------------------
__global__ void k3_attn(const float* __restrict__ fc1w, const float* __restrict__ fc1b,
                        const float* __restrict__ fc2w, const float* __restrict__ fc2b)
{
    const int b = blockIdx.x, lane = threadIdx.x;
    float s0 = 0.f, s1 = 0.f, s2 = 0.f, s3 = 0.f;
    for (int c = lane; c < C2_; c += 32) {
        float pv = g_mu[b*C2_ + c];
        s0 += pv * fc1w[0*C2_ + c];
        s1 += pv * fc1w[1*C2_ + c];
        s2 += pv * fc1w[2*C2_ + c];
        s3 += pv * fc1w[3*C2_ + c];
    }
#pragma unroll
    for (int off = 16; off; off >>= 1) {
        s0 += __shfl_down_sync(0xffffffffu, s0, off);
        s1 += __shfl_down_sync(0xffffffffu, s1, off);
        s2 += __shfl_down_sync(0xffffffffu, s2, off);
        s3 += __shfl_down_sync(0xffffffffu, s3, off);
    }
    if (lane == 0) {
        float a[4];
        a[0] = fmaxf(s0 + fc1b[0], 0.f);
        a[1] = fmaxf(s1 + fc1b[1], 0.f);
        a[2] = fmaxf(s2 + fc1b[2], 0.f);
        a[3] = fmaxf(s3 + fc1b[3], 0.f);
        float l[4];
#pragma unroll
        for (int j = 0; j < 4; ++j)
            l[j] = a[0]*fc2w[j*4+0] + a[1]*fc2w[j*4+1] + a[2]*fc2w[j*4+2] + a[3]*fc2w[j*4+3] + fc2b[j];
        float m = fmaxf(fmaxf(l[0], l[1]), fmaxf(l[2], l[3]));
        float e[4], den = 0.f;
#pragma unroll
        for (int j = 0; j < 4; ++j) { e[j] = expf(l[j] - m); den += e[j]; }
        float inv = 1.f / den;
#pragma unroll
        for (int j = 0; j < 4; ++j) g_attn[b*4 + j] = e[j] * inv;
    }
}

// ---------------------------------------------------------------------------
// K4: aggregate weights, FOLD rstd, split fp16 hi/lo into MMA layout
// ---------------------------------------------------------------------------
__global__ __launch_bounds__(256)
void k4_aggw(const float* __restrict__ dyw)
{
    size_t idx = (size_t)blockIdx.x*256 + threadIdx.x;   // 16*2*32*128*88
    int k = (int)(idx % KCH);
    size_t r = idx / KCH;
    int o  = (int)(r % 128); r /= 128;
    int ch = (int)(r % NCH); r /= NCH;
    int og = (int)(r % 2);
    int b  = (int)(r / 2);

    float v = 0.f;
    if (k < 72) {
        int q  = k >> 3;
        int ci = ch*8 + (k & 7);
        int oi = og*128 + o;
        const size_t ks = (size_t)C2_*C2_*9;
        size_t base = ((size_t)oi*C2_ + ci)*9 + q;
        v = g_attn[b*4+0]*__ldg(&dyw[base])
          + g_attn[b*4+1]*__ldg(&dyw[base + ks])
          + g_attn[b*4+2]*__ldg(&dyw[base + 2*ks])
          + g_attn[b*4+3]*__ldg(&dyw[base + 3*ks]);
        v *= g_rstd[b*C2_ + ci];     // fold InstanceNorm scale
    }
    __half vh = __float2half_rn(v);
    float vl = v - __half2float(vh);
    size_t outb = ((((size_t)b*2 + og)*NCH + ch)*2)*(size_t)(128*KCH) + (size_t)o*KCH + k;
    g_wm[outb] = vh;
    g_wm[outb + 128*KCH] = __float2half_rn(vl);
}

// K4b: agg_b[b,o]
__global__ void k4_aggb(const float* __restrict__ dyb)
{
    int idx = blockIdx.x*256 + threadIdx.x;   // 4096
    int b = idx >> 8, o = idx & 255;
    float v = 0.f;
#pragma unroll
    for (int k = 0; k < 4; ++k) v += g_attn[b*4+k] * dyb[k*C2_ + o];
    g_aggb[idx] = v;
}

// K4c: Cq[b,o,q] = sum_ci w_agg[b,o,ci,q] * mu[ci]*rstd[ci];  Cqt = sum_q Cq
// block per (o, b), 288 threads (32 ci_w x 9 q), coalesced dyw reads
__global__ __launch_bounds__(288)
void k4c_cq(const float* __restrict__ dyw)
{
    __shared__ float sh[32][9];
    __shared__ float shc[9];
    const int o = blockIdx.x, b = blockIdx.y;
    const int tid = threadIdx.x;
    const int ciw = tid / 9, q = tid - ciw*9;

    const float a0 = g_attn[b*4+0], a1 = g_attn[b*4+1];
    const float a2 = g_attn[b*4+2], a3 = g_attn[b*4+3];
    const size_t ks = (size_t)C2_*C2_*9;
    float acc = 0.f;
    for (int ci = ciw; ci < C2_; ci += 32) {
        size_t base = ((size_t)o*C2_ + ci)*9 + q;
        float wv = a0*dyw[base] + a1*dyw[base+ks] + a2*dyw[base+2*ks] + a3*dyw[base+3*ks];
        acc += wv * g_mr[b*C2_ + ci];
    }
    sh[ciw][q] = acc;
    __syncthreads();
    if (tid < 9) {
        float s = 0.f;
#pragma unroll
        for (int i = 0; i < 32; ++i) s += sh[i][tid];
        g_cq[(b*C2_+o)*9 + tid] = s;
        shc[tid] = s;
    }
    __syncthreads();
    if (tid == 0) {
        float s = 0.f;
#pragma unroll
        for (int i = 0; i < 9; ++i) s += shc[i];
        g_cqt[b*C2_+o] = s;
    }
}

// ---------------------------------------------------------------------------
// K5: tensor-core implicit-GEMM 3x3 conv, 2-pass fp16 (A hi/lo, B single),
//     epilogue: -Cqt fold + border Cq fixup + agg bias + bn1
// ---------------------------------------------------------------------------
__device__ __forceinline__ void mma16816(float* d, const uint32_t* a, const uint32_t* bb)
{
    asm volatile(
        "mma.sync.aligned.m16n8k16.row.col.f32.f16.f16.f32 "
        "{%0,%1,%2,%3}, {%4,%5,%6,%7}, {%8,%9}, {%0,%1,%2,%3};"
        : "+f"(d[0]), "+f"(d[1]), "+f"(d[2]), "+f"(d[3])
        : "r"(a[0]), "r"(a[1]), "r"(a[2]), "r"(a[3]), "r"(bb[0]), "r"(bb[1]));
}

__global__ __launch_bounds__(256)
void k5_mma(const float* __restrict__ g1, const float* __restrict__ b1,
            const float* __restrict__ m1, const float* __restrict__ v1,
            float* __restrict__ out)
{
    __shared__ __align__(16) __half As[2][128*KCH];   // [half][o*KCH+k]
    __shared__ __align__(16) __half Bs[108*8];        // [pix*8+ci]

    const int b    = blockIdx.z;
    const int og   = blockIdx.y;
    const int tile = blockIdx.x;                 // 0..99
    const int h0 = (tile/5)*4, w0 = (tile%5)*16;
    const int tid  = threadIdx.x;
    const int lane = tid & 31, warp = tid >> 5;
    const int warp_m = warp & 3, warp_n = warp >> 2;

    float acc[2][4][4];
#pragma unroll
    for (int mr = 0; mr < 2; ++mr)
#pragma unroll
        for (int nr = 0; nr < 4; ++nr)
#pragma unroll
            for (int j = 0; j < 4; ++j) acc[mr][nr][j] = 0.f;

    const __half* wsrc = g_wm + (((size_t)b*2 + og)*NCH)*2*(size_t)(128*KCH);

    // B staging: threads 0..107, one pixel each (8 fp16 = int4)
    const int st_px = tid;
    const int st_r = st_px/18, st_c = st_px - st_r*18;
    const int gh = h0 + st_r - 1, gw = w0 + st_c - 1;
    const bool st_ok = (tid < 108) && gh >= 0 && gh < H_ && gw >= 0 && gw < W_;
    const int ghc = max(0, min(H_-1, gh)), gwc = max(0, min(W_-1, gw));
    const size_t st_src0 = ((size_t)b*P_ + ghc*W_ + gwc)*(size_t)C2_;

    // shift tables (q0 = 2s, q1 = 2s+1; s=4 -> q1=9 dummy)
    const int DY0[5] = {0,0,1,2,2}, DX0[5] = {0,2,1,0,2};
    const int DY1[5] = {0,1,1,2,0}, DX1[5] = {1,0,2,1,0};

    for (int ch = 0; ch < NCH; ++ch) {
        // stage A (45056 B contiguous)
        const int4* asrc = (const int4*)(wsrc + (size_t)ch*2*128*KCH);
        int4* adst = (int4*)&As[0][0];
#pragma unroll
        for (int i = 0; i < 11; ++i)
            adst[tid + 256*i] = asrc[tid + 256*i];
        // stage B halo tile
        if (tid < 108) {
            int4 vv = make_int4(0,0,0,0);
            if (st_ok) vv = *(const int4*)(g_ym + st_src0 + ch*8);
            *(int4*)&Bs[st_px*8] = vv;
        }
        __syncthreads();

#pragma unroll
        for (int s = 0; s < 5; ++s) {
            uint32_t ah[2][4], al[2][4];
            const int kb = 16*s + 2*(lane&3);
#pragma unroll
            for (int mr = 0; mr < 2; ++mr) {
                int o = warp_m*32 + mr*16 + (lane>>2);
                const uint32_t* ph  = (const uint32_t*)&As[0][o*KCH + kb];
                const uint32_t* ph8 = (const uint32_t*)&As[0][(o+8)*KCH + kb];
                const uint32_t* pl  = (const uint32_t*)&As[1][o*KCH + kb];
                const uint32_t* pl8 = (const uint32_t*)&As[1][(o+8)*KCH + kb];
                ah[mr][0] = ph[0];  ah[mr][1] = ph8[0];  ah[mr][2] = ph[4];  ah[mr][3] = ph8[4];
                al[mr][0] = pl[0];  al[mr][1] = pl8[0];  al[mr][2] = pl[4];  al[mr][3] = pl8[4];
            }
            const int dy0 = DY0[s], dx0 = DX0[s], dy1 = DY1[s], dx1 = DX1[s];
            uint32_t bh[4][2];
#pragma unroll
            for (int nr = 0; nr < 4; ++nr) {
                int pr = warp_n*2 + (nr>>1);
                int pc = (nr&1)*8 + (lane>>2);
                int i0 = ((pr+dy0)*18 + pc+dx0)*8 + 2*(lane&3);
                int i1 = ((pr+dy1)*18 + pc+dx1)*8 + 2*(lane&3);
                bh[nr][0] = *(const uint32_t*)&Bs[i0];
                bh[nr][1] = *(const uint32_t*)&Bs[i1];
            }
            // 2-pass: Ahi*B + Alo*B
#pragma unroll
            for (int mr = 0; mr < 2; ++mr)
#pragma unroll
                for (int nr = 0; nr < 4; ++nr) {
                    mma16816(acc[mr][nr], ah[mr], bh[nr]);
                    mma16816(acc[mr][nr], al[mr], bh[nr]);
                }
        }
        __syncthreads();
    }

    // Epilogue: res = (acc + borderfix)*s + ((aggb - Cqt - m1)*s + b1)
    const int obase = og*128 + warp_m*32;
#pragma unroll
    for (int mr = 0; mr < 2; ++mr) {
        const int o_a = obase + mr*16 + (lane>>2);
        const int o_b = o_a + 8;
        float sA = __ldg(&g1[o_a]) * rsqrtf(__ldg(&v1[o_a]) + EPS_);
        float offA = (__ldg(&g_aggb[b*C2_+o_a]) - g_cqt[b*C2_+o_a] - __ldg(&m1[o_a]))*sA + __ldg(&b1[o_a]);
        float sB = __ldg(&g1[o_b]) * rsqrtf(__ldg(&v1[o_b]) + EPS_);
        float offB = (__ldg(&g_aggb[b*C2_+o_b]) - g_cqt[b*C2_+o_b] - __ldg(&m1[o_b]))*sB + __ldg(&b1[o_b]);
#pragma unroll
        for (int nr = 0; nr < 4; ++nr) {
            int pr = warp_n*2 + (nr>>1);
            int pc = (nr&1)*8 + 2*(lane&3);
            int h = h0 + pr, w1 = w0 + pc, w2 = w1 + 1;
            float fA1 = 0.f, fA2 = 0.f, fB1 = 0.f, fB2 = 0.f;
            if (h == 0 || h == H_-1 || w1 == 0 || w2 == W_-1) {
#pragma unroll
                for (int q = 0; q < 9; ++q) {
                    int dy = q/3 - 1, dx = q - (q/3)*3 - 1;
                    bool ro = (unsigned)(h+dy) >= (unsigned)H_;
                    bool c1 = ro || (unsigned)(w1+dx) >= (unsigned)W_;
                    bool c2 = ro || (unsigned)(w2+dx) >= (unsigned)W_;
                    if (c1 | c2) {
                        float ca = g_cq[(b*C2_+o_a)*9 + q];
                        float cb = g_cq[(b*C2_+o_b)*9 + q];
                        if (c1) { fA1 += ca; fB1 += cb; }
                        if (c2) { fA2 += ca; fB2 += cb; }
                    }
                }
            }
            size_t po = (size_t)h*W_ + w1;
            float2 vA, vB;
            vA.x = (acc[mr][nr][0]+fA1)*sA + offA;  vA.y = (acc[mr][nr][1]+fA2)*sA + offA;
            vB.x = (acc[mr][nr][2]+fB1)*sB + offB;  vB.y = (acc[mr][nr][3]+fB2)*sB + offB;
            *(float2*)&out[((size_t)(b*C2_+o_a))*P_ + po] = vA;
            *(float2*)&out[((size_t)(b*C2_+o_b))*P_ + po] = vB;
        }
    }
}

// ---------------------------------------------------------------------------
extern "C" void kernel_launch(void* const* d_in, const int* in_sizes, int n_in,
                              void* d_out, int out_size)
{
    const float* x      = (const float*)d_in[0];
    const float* conv1w = (const float*)d_in[1];
    const float* bng    = (const float*)d_in[2];
    const float* bnb    = (const float*)d_in[3];
    const float* bnm    = (const float*)d_in[4];
    const float* bnv    = (const float*)d_in[5];
    const float* fc1w   = (const float*)d_in[6];
    const float* fc1b   = (const float*)d_in[7];
    const float* fc2w   = (const float*)d_in[8];
    const float* fc2b   = (const float*)d_in[9];
    const float* dyw    = (const float*)d_in[10];
    const float* dyb    = (const float*)d_in[11];
    const float* g1     = (const float*)d_in[12];
    const float* b1     = (const float*)d_in[13];
    const float* m1     = (const float*)d_in[14];
    const float* v1     = (const float*)d_in[15];
    float* out = (float*)d_out;

    k1_conv1<<<dim3(P_/64, C2_/64, B_), 256>>>(x, conv1w, bng, bnb, bnm, bnv);
    k2_fin<<<B_*C2_/256, 256>>>();
    k3_attn<<<B_, 32>>>(fc1w, fc1b, fc2w, fc2b);
    k4_aggw<<<(int)(((size_t)B_*2*NCH*128*KCH)/256), 256>>>(dyw);
    k4_aggb<<<B_*C2_/256, 256>>>(dyb);
    k4c_cq<<<dim3(C2_, B_), 288>>>(dyw);
    k5_mma<<<dim3(100, 2, B_), 256>>>(g1, b1, m1, v1, out);
}

// round 7
// speedup vs baseline: 7.8457x; 1.6090x over previous
#include <cuda_runtime.h>
#include <cuda_fp16.h>
#include <cstdint>
#include <cstddef>

// Problem constants
#define B_  16
#define C1_ 128
#define C2_ 256
#define H_  80
#define W_  80
#define P_  (H_*W_)           // 6400
#define EPS_ 1e-5f

#define KCH 88                // padded k per ci-chunk (9 taps*8ci=72 -> +dummy tap -> 80 -> pad 88)
#define NCH 32                // ci-chunks (256/8)

// Scratch (device globals)
__device__ float g_ps [B_*C2_*128];       // per-(b,o) partial sums over 100 px-tiles
__device__ float g_ps2[B_*C2_*128];
__device__ float g_mu[B_*C2_];
__device__ float g_rstd[B_*C2_];
__device__ float g_mr[B_*C2_];            // mu*rstd
__device__ float g_attn[B_*4];
__device__ float g_aggb[B_*C2_];
__device__ float g_cq [B_*C2_*9];         // Cq[b,o,q] = sum_ci w_agg*mu*rstd
__device__ float g_cqt[B_*C2_];           // sum_q Cq
// MMA weights (rstd-folded, fp16 hi only): [b][og2][ch32][o128][KCH] (~23 MB)
__device__ __align__(16) __half g_wm[(size_t)B_*2*NCH*128*KCH];
// MMA input y (fp16): [b][pix6400][ci256] (~52 MB)
__device__ __align__(16) __half g_ym[(size_t)B_*P_*C2_];

// ---------------------------------------------------------------------------
// K1: y = silu(bn(conv1x1(x)))  -> fp16 transposed write to g_ym
//     + deterministic per-block partial sums for InstanceNorm stats
// ---------------------------------------------------------------------------
__global__ __launch_bounds__(256)
void k1_conv1(const float* __restrict__ x, const float* __restrict__ w,
              const float* __restrict__ bng, const float* __restrict__ bnb,
              const float* __restrict__ bnm, const float* __restrict__ bnv)
{
    __shared__ float As[32][68];
    __shared__ float Bs[32][68];
    __shared__ __half shm[64][72];      // [px][o], padded row vs conflicts

    const int b  = blockIdx.z;
    const int o0 = blockIdx.y * 64;
    const int p0 = blockIdx.x * 64;
    const int tid = threadIdx.x;
    const int tx = tid & 15, ty = tid >> 4;

    float acc[4][4];
#pragma unroll
    for (int j = 0; j < 4; ++j)
#pragma unroll
        for (int i = 0; i < 4; ++i) acc[j][i] = 0.f;

    for (int c0 = 0; c0 < C1_; c0 += 32) {
#pragma unroll
        for (int r = 0; r < 8; ++r) {
            int l = tid + 256*r;
            int o = l >> 5, c = l & 31;
            As[c][o] = w[(o0+o)*C1_ + c0 + c];
        }
#pragma unroll
        for (int r = 0; r < 2; ++r) {
            int l = tid + 256*r;
            int c = l >> 4, p4 = l & 15;
            float4 v = *(const float4*)(x + ((size_t)(b*C1_ + c0 + c))*P_ + p0 + p4*4);
            *(float4*)&Bs[c][p4*4] = v;
        }
        __syncthreads();
#pragma unroll
        for (int kk = 0; kk < 32; ++kk) {
            float4 av = *(const float4*)&As[kk][ty*4];
            float4 bv = *(const float4*)&Bs[kk][tx*4];
            float ar[4] = {av.x, av.y, av.z, av.w};
            float br[4] = {bv.x, bv.y, bv.z, bv.w};
#pragma unroll
            for (int j = 0; j < 4; ++j)
#pragma unroll
                for (int i = 0; i < 4; ++i) acc[j][i] += ar[j]*br[i];
        }
        __syncthreads();
    }

    // bn + silu; stash fp16 in smem; accumulate per-o partial sums
    float ps[4], ps2[4];
#pragma unroll
    for (int j = 0; j < 4; ++j) {
        int o = o0 + ty*4 + j;
        float s = bng[o] * rsqrtf(bnv[o] + EPS_);
        float t = bnb[o] - bnm[o]*s;
        ps[j] = 0.f; ps2[j] = 0.f;
#pragma unroll
        for (int i = 0; i < 4; ++i) {
            float vv = acc[j][i]*s + t;
            vv = vv / (1.f + expf(-vv));
            ps[j]  += vv;
            ps2[j] += vv*vv;
            shm[tx*4+i][ty*4+j] = __float2half_rn(vv);
        }
    }
#pragma unroll
    for (int off = 1; off <= 8; off <<= 1) {
#pragma unroll
        for (int j = 0; j < 4; ++j) {
            ps[j]  += __shfl_xor_sync(0xffffffffu, ps[j],  off);
            ps2[j] += __shfl_xor_sync(0xffffffffu, ps2[j], off);
        }
    }
    if (tx == 0) {
#pragma unroll
        for (int j = 0; j < 4; ++j) {
            int o = o0 + ty*4 + j;
            g_ps [(b*C2_+o)*128 + blockIdx.x] = ps[j];
            g_ps2[(b*C2_+o)*128 + blockIdx.x] = ps2[j];
        }
    }
    __syncthreads();
    // coalesced transposed write: g_ym[b][px][ci]
#pragma unroll
    for (int r = 0; r < 2; ++r) {
        int l = tid + 256*r;
        int px = l >> 3, seg = l & 7;
        *(int4*)(g_ym + ((size_t)b*P_ + p0 + px)*C2_ + o0 + seg*8) =
            *(const int4*)&shm[px][seg*8];
    }
}

// ---------------------------------------------------------------------------
// K2: finalize stats
// ---------------------------------------------------------------------------
__global__ void k2_fin()
{
    int idx = blockIdx.x*256 + threadIdx.x;   // b*C2 + o
    float s = 0.f, s2 = 0.f;
    for (int t = 0; t < 100; ++t) {
        s  += g_ps [idx*128 + t];
        s2 += g_ps2[idx*128 + t];
    }
    float mu  = s  * (1.f / P_);
    float var = s2 * (1.f / P_) - mu*mu;
    float rs  = rsqrtf(fmaxf(var, 0.f) + EPS_);
    g_mu[idx]   = mu;
    g_rstd[idx] = rs;
    g_mr[idx]   = mu * rs;
}

// ---------------------------------------------------------------------------
// K3: attention (one warp per sample)
// ---------------------------------------------------------------------------
__global__ void k3_attn(const float* __restrict__ fc1w, const float* __restrict__ fc1b,
                        const float* __restrict__ fc2w, const float* __restrict__ fc2b)
{
    const int b = blockIdx.x, lane = threadIdx.x;
    float s0 = 0.f, s1 = 0.f, s2 = 0.f, s3 = 0.f;
    for (int c = lane; c < C2_; c += 32) {
        float pv = g_mu[b*C2_ + c];
        s0 += pv * fc1w[0*C2_ + c];
        s1 += pv * fc1w[1*C2_ + c];
        s2 += pv * fc1w[2*C2_ + c];
        s3 += pv * fc1w[3*C2_ + c];
    }
#pragma unroll
    for (int off = 16; off; off >>= 1) {
        s0 += __shfl_down_sync(0xffffffffu, s0, off);
        s1 += __shfl_down_sync(0xffffffffu, s1, off);
        s2 += __shfl_down_sync(0xffffffffu, s2, off);
        s3 += __shfl_down_sync(0xffffffffu, s3, off);
    }
    if (lane == 0) {
        float a[4];
        a[0] = fmaxf(s0 + fc1b[0], 0.f);
        a[1] = fmaxf(s1 + fc1b[1], 0.f);
        a[2] = fmaxf(s2 + fc1b[2], 0.f);
        a[3] = fmaxf(s3 + fc1b[3], 0.f);
        float l[4];
#pragma unroll
        for (int j = 0; j < 4; ++j)
            l[j] = a[0]*fc2w[j*4+0] + a[1]*fc2w[j*4+1] + a[2]*fc2w[j*4+2] + a[3]*fc2w[j*4+3] + fc2b[j];
        float m = fmaxf(fmaxf(l[0], l[1]), fmaxf(l[2], l[3]));
        float e[4], den = 0.f;
#pragma unroll
        for (int j = 0; j < 4; ++j) { e[j] = expf(l[j] - m); den += e[j]; }
        float inv = 1.f / den;
#pragma unroll
        for (int j = 0; j < 4; ++j) g_attn[b*4 + j] = e[j] * inv;
    }
}

// ---------------------------------------------------------------------------
// K4: aggregate weights, FOLD rstd, fp16 (hi only) into MMA layout
// ---------------------------------------------------------------------------
__global__ __launch_bounds__(256)
void k4_aggw(const float* __restrict__ dyw)
{
    size_t idx = (size_t)blockIdx.x*256 + threadIdx.x;   // 16*2*32*128*88
    int k = (int)(idx % KCH);
    size_t r = idx / KCH;
    int o  = (int)(r % 128); r /= 128;
    int ch = (int)(r % NCH); r /= NCH;
    int og = (int)(r % 2);
    int b  = (int)(r / 2);

    float v = 0.f;
    if (k < 72) {
        int q  = k >> 3;
        int ci = ch*8 + (k & 7);
        int oi = og*128 + o;
        const size_t ks = (size_t)C2_*C2_*9;
        size_t base = ((size_t)oi*C2_ + ci)*9 + q;
        v = g_attn[b*4+0]*__ldg(&dyw[base])
          + g_attn[b*4+1]*__ldg(&dyw[base + ks])
          + g_attn[b*4+2]*__ldg(&dyw[base + 2*ks])
          + g_attn[b*4+3]*__ldg(&dyw[base + 3*ks]);
        v *= g_rstd[b*C2_ + ci];     // fold InstanceNorm scale
    }
    size_t outb = (((size_t)b*2 + og)*NCH + ch)*(size_t)(128*KCH) + (size_t)o*KCH + k;
    g_wm[outb] = __float2half_rn(v);
}

// K4b: agg_b[b,o]
__global__ void k4_aggb(const float* __restrict__ dyb)
{
    int idx = blockIdx.x*256 + threadIdx.x;   // 4096
    int b = idx >> 8, o = idx & 255;
    float v = 0.f;
#pragma unroll
    for (int k = 0; k < 4; ++k) v += g_attn[b*4+k] * dyb[k*C2_ + o];
    g_aggb[idx] = v;
}

// K4c: Cq[b,o,q] = sum_ci w_agg[b,o,ci,q] * mu[ci]*rstd[ci];  Cqt = sum_q Cq
__global__ __launch_bounds__(288)
void k4c_cq(const float* __restrict__ dyw)
{
    __shared__ float sh[32][9];
    __shared__ float shc[9];
    const int o = blockIdx.x, b = blockIdx.y;
    const int tid = threadIdx.x;
    const int ciw = tid / 9, q = tid - ciw*9;

    const float a0 = g_attn[b*4+0], a1 = g_attn[b*4+1];
    const float a2 = g_attn[b*4+2], a3 = g_attn[b*4+3];
    const size_t ks = (size_t)C2_*C2_*9;
    float acc = 0.f;
    for (int ci = ciw; ci < C2_; ci += 32) {
        size_t base = ((size_t)o*C2_ + ci)*9 + q;
        float wv = a0*dyw[base] + a1*dyw[base+ks] + a2*dyw[base+2*ks] + a3*dyw[base+3*ks];
        acc += wv * g_mr[b*C2_ + ci];
    }
    sh[ciw][q] = acc;
    __syncthreads();
    if (tid < 9) {
        float s = 0.f;
#pragma unroll
        for (int i = 0; i < 32; ++i) s += sh[i][tid];
        g_cq[(b*C2_+o)*9 + tid] = s;
        shc[tid] = s;
    }
    __syncthreads();
    if (tid == 0) {
        float s = 0.f;
#pragma unroll
        for (int i = 0; i < 9; ++i) s += shc[i];
        g_cqt[b*C2_+o] = s;
    }
}

// ---------------------------------------------------------------------------
// K5: tensor-core implicit-GEMM 3x3 conv, 1-pass fp16,
//     tile = 128 o x 128 px (8 rows x 16 cols). 8 warps = 4M x 2N.
//     epilogue: -Cqt fold + border Cq fixup + agg bias + bn1
// ---------------------------------------------------------------------------
__device__ __forceinline__ void mma16816(float* d, const uint32_t* a, const uint32_t* bb)
{
    asm volatile(
        "mma.sync.aligned.m16n8k16.row.col.f32.f16.f16.f32 "
        "{%0,%1,%2,%3}, {%4,%5,%6,%7}, {%8,%9}, {%0,%1,%2,%3};"
        : "+f"(d[0]), "+f"(d[1]), "+f"(d[2]), "+f"(d[3])
        : "r"(a[0]), "r"(a[1]), "r"(a[2]), "r"(a[3]), "r"(bb[0]), "r"(bb[1]));
}

__global__ __launch_bounds__(256)
void k5_mma(const float* __restrict__ g1, const float* __restrict__ b1,
            const float* __restrict__ m1, const float* __restrict__ v1,
            float* __restrict__ out)
{
    __shared__ __align__(16) __half As[128*KCH];   // weights hi [o*KCH+k]   (22.5KB)
    __shared__ __align__(16) __half Bs[180*8];     // halo pixels [pix*8+ci] (2.9KB)

    const int b    = blockIdx.z;
    const int og   = blockIdx.y;
    const int tile = blockIdx.x;                 // 0..49
    const int h0 = (tile/5)*8, w0 = (tile%5)*16;
    const int tid  = threadIdx.x;
    const int lane = tid & 31, warp = tid >> 5;
    const int warp_m = warp & 3, warp_n = warp >> 2;

    float acc[2][8][4];
#pragma unroll
    for (int mr = 0; mr < 2; ++mr)
#pragma unroll
        for (int nr = 0; nr < 8; ++nr)
#pragma unroll
            for (int j = 0; j < 4; ++j) acc[mr][nr][j] = 0.f;

    const __half* wsrc = g_wm + (((size_t)b*2 + og)*NCH)*(size_t)(128*KCH);

    // B staging: threads 0..179, one halo pixel each (8 fp16 = int4); 10x18 halo
    const int st_px = tid;
    const int st_r = st_px/18, st_c = st_px - st_r*18;
    const int gh = h0 + st_r - 1, gw = w0 + st_c - 1;
    const bool st_ok = (tid < 180) && gh >= 0 && gh < H_ && gw >= 0 && gw < W_;
    const int ghc = max(0, min(H_-1, gh)), gwc = max(0, min(W_-1, gw));
    const size_t st_src0 = ((size_t)b*P_ + ghc*W_ + gwc)*(size_t)C2_;

    // shift tables (q0 = 2s, q1 = 2s+1; s=4 -> q1=9 dummy)
    const int DY0[5] = {0,0,1,2,2}, DX0[5] = {0,2,1,0,2};
    const int DY1[5] = {0,1,1,2,0}, DX1[5] = {1,0,2,1,0};

    for (int ch = 0; ch < NCH; ++ch) {
        // stage A (22528 B = 1408 int4)
        const int4* asrc = (const int4*)(wsrc + (size_t)ch*128*KCH);
        int4* adst = (int4*)&As[0];
#pragma unroll
        for (int i = 0; i < 6; ++i) {
            int idx = tid + 256*i;
            if (idx < 1408) adst[idx] = asrc[idx];
        }
        // stage B halo tile
        if (tid < 180) {
            int4 vv = make_int4(0,0,0,0);
            if (st_ok) vv = *(const int4*)(g_ym + st_src0 + ch*8);
            *(int4*)&Bs[st_px*8] = vv;
        }
        __syncthreads();

#pragma unroll
        for (int s = 0; s < 5; ++s) {
            uint32_t ah[2][4];
            const int kb = 16*s + 2*(lane&3);
#pragma unroll
            for (int mr = 0; mr < 2; ++mr) {
                int o = warp_m*32 + mr*16 + (lane>>2);
                const uint32_t* ph  = (const uint32_t*)&As[o*KCH + kb];
                const uint32_t* ph8 = (const uint32_t*)&As[(o+8)*KCH + kb];
                ah[mr][0] = ph[0];  ah[mr][1] = ph8[0];  ah[mr][2] = ph[4];  ah[mr][3] = ph8[4];
            }
            const int dy0 = DY0[s], dx0 = DX0[s], dy1 = DY1[s], dx1 = DX1[s];
            uint32_t bh[8][2];
#pragma unroll
            for (int nr = 0; nr < 8; ++nr) {
                int pr = warp_n*4 + (nr>>1);
                int pc = (nr&1)*8 + (lane>>2);
                int i0 = ((pr+dy0)*18 + pc+dx0)*8 + 2*(lane&3);
                int i1 = ((pr+dy1)*18 + pc+dx1)*8 + 2*(lane&3);
                bh[nr][0] = *(const uint32_t*)&Bs[i0];
                bh[nr][1] = *(const uint32_t*)&Bs[i1];
            }
#pragma unroll
            for (int mr = 0; mr < 2; ++mr)
#pragma unroll
                for (int nr = 0; nr < 8; ++nr)
                    mma16816(acc[mr][nr], ah[mr], bh[nr]);
        }
        __syncthreads();
    }

    // Epilogue: res = (acc + borderfix)*s + ((aggb - Cqt - m1)*s + b1)
    const int obase = og*128 + warp_m*32;
#pragma unroll
    for (int mr = 0; mr < 2; ++mr) {
        const int o_a = obase + mr*16 + (lane>>2);
        const int o_b = o_a + 8;
        float sA = __ldg(&g1[o_a]) * rsqrtf(__ldg(&v1[o_a]) + EPS_);
        float offA = (__ldg(&g_aggb[b*C2_+o_a]) - g_cqt[b*C2_+o_a] - __ldg(&m1[o_a]))*sA + __ldg(&b1[o_a]);
        float sB = __ldg(&g1[o_b]) * rsqrtf(__ldg(&v1[o_b]) + EPS_);
        float offB = (__ldg(&g_aggb[b*C2_+o_b]) - g_cqt[b*C2_+o_b] - __ldg(&m1[o_b]))*sB + __ldg(&b1[o_b]);
#pragma unroll
        for (int nr = 0; nr < 8; ++nr) {
            int pr = warp_n*4 + (nr>>1);
            int pc = (nr&1)*8 + 2*(lane&3);
            int h = h0 + pr, w1 = w0 + pc, w2 = w1 + 1;
            float fA1 = 0.f, fA2 = 0.f, fB1 = 0.f, fB2 = 0.f;
            if (h == 0 || h == H_-1 || w1 == 0 || w2 == W_-1) {
#pragma unroll
                for (int q = 0; q < 9; ++q) {
                    int dy = q/3 - 1, dx = q - (q/3)*3 - 1;
                    bool ro = (unsigned)(h+dy) >= (unsigned)H_;
                    bool c1 = ro || (unsigned)(w1+dx) >= (unsigned)W_;
                    bool c2 = ro || (unsigned)(w2+dx) >= (unsigned)W_;
                    if (c1 | c2) {
                        float ca = g_cq[(b*C2_+o_a)*9 + q];
                        float cb = g_cq[(b*C2_+o_b)*9 + q];
                        if (c1) { fA1 += ca; fB1 += cb; }
                        if (c2) { fA2 += ca; fB2 += cb; }
                    }
                }
            }
            size_t po = (size_t)h*W_ + w1;
            float2 vA, vB;
            vA.x = (acc[mr][nr][0]+fA1)*sA + offA;  vA.y = (acc[mr][nr][1]+fA2)*sA + offA;
            vB.x = (acc[mr][nr][2]+fB1)*sB + offB;  vB.y = (acc[mr][nr][3]+fB2)*sB + offB;
            *(float2*)&out[((size_t)(b*C2_+o_a))*P_ + po] = vA;
            *(float2*)&out[((size_t)(b*C2_+o_b))*P_ + po] = vB;
        }
    }
}

// ---------------------------------------------------------------------------
extern "C" void kernel_launch(void* const* d_in, const int* in_sizes, int n_in,
                              void* d_out, int out_size)
{
    const float* x      = (const float*)d_in[0];
    const float* conv1w = (const float*)d_in[1];
    const float* bng    = (const float*)d_in[2];
    const float* bnb    = (const float*)d_in[3];
    const float* bnm    = (const float*)d_in[4];
    const float* bnv    = (const float*)d_in[5];
    const float* fc1w   = (const float*)d_in[6];
    const float* fc1b   = (const float*)d_in[7];
    const float* fc2w   = (const float*)d_in[8];
    const float* fc2b   = (const float*)d_in[9];
    const float* dyw    = (const float*)d_in[10];
    const float* dyb    = (const float*)d_in[11];
    const float* g1     = (const float*)d_in[12];
    const float* b1     = (const float*)d_in[13];
    const float* m1     = (const float*)d_in[14];
    const float* v1     = (const float*)d_in[15];
    float* out = (float*)d_out;

    k1_conv1<<<dim3(P_/64, C2_/64, B_), 256>>>(x, conv1w, bng, bnb, bnm, bnv);
    k2_fin<<<B_*C2_/256, 256>>>();
    k3_attn<<<B_, 32>>>(fc1w, fc1b, fc2w, fc2b);
    k4_aggw<<<(int)(((size_t)B_*2*NCH*128*KCH)/256), 256>>>(dyw);
    k4_aggb<<<B_*C2_/256, 256>>>(dyb);
    k4c_cq<<<dim3(C2_, B_), 288>>>(dyw);
    k5_mma<<<dim3(50, 2, B_), 256>>>(g1, b1, m1, v1, out);
}

// round 8
// speedup vs baseline: 10.1821x; 1.2978x over previous
#include <cuda_runtime.h>
#include <cuda_fp16.h>
#include <cstdint>
#include <cstddef>

// Problem constants
#define B_  16
#define C1_ 128
#define C2_ 256
#define H_  80
#define W_  80
#define P_  (H_*W_)           // 6400
#define EPS_ 1e-5f

#define KCH 88                // padded k per ci-chunk (9 taps*8ci=72 -> +dummy tap -> 80 -> pad 88)
#define NCH 32                // ci-chunks (256/8)

// Scratch (device globals)
__device__ float g_ps [B_*C2_*128];       // [tile][b*C2+o] partial sums (50 tiles used)
__device__ float g_ps2[B_*C2_*128];
__device__ float g_mu[B_*C2_];
__device__ float g_rstd[B_*C2_];
__device__ float g_mr[B_*C2_];            // mu*rstd
__device__ float g_attn[B_*4];
__device__ float g_aggb[B_*C2_];
__device__ float g_cq [B_*C2_*9];         // Cq[b,o,q]
__device__ float g_cqt[B_*C2_];           // sum_q Cq
// conv1 weights split fp16 hi/lo: [og2][ch4][half2][o128][40]
__device__ __align__(16) __half g_wh[2*4*2*128*40];
// MMA weights (rstd-folded, fp16 hi only): [b][og2][ch32][o128][KCH] (~23 MB)
__device__ __align__(16) __half g_wm[(size_t)B_*2*NCH*128*KCH];
// MMA input y (fp16): [b][pix6400][ci256] (~52 MB)
__device__ __align__(16) __half g_ym[(size_t)B_*P_*C2_];

__device__ __forceinline__ void mma16816(float* d, const uint32_t* a, const uint32_t* bb)
{
    asm volatile(
        "mma.sync.aligned.m16n8k16.row.col.f32.f16.f16.f32 "
        "{%0,%1,%2,%3}, {%4,%5,%6,%7}, {%8,%9}, {%0,%1,%2,%3};"
        : "+f"(d[0]), "+f"(d[1]), "+f"(d[2]), "+f"(d[3])
        : "r"(a[0]), "r"(a[1]), "r"(a[2]), "r"(a[3]), "r"(bb[0]), "r"(bb[1]));
}

// ---------------------------------------------------------------------------
// K0: split conv1 weights into fp16 hi/lo, smem-image layout [og][ch][hl][o][40]
// ---------------------------------------------------------------------------
__global__ __launch_bounds__(256)
void k0_wsplit(const float* __restrict__ w)
{
    int idx = blockIdx.x*256 + threadIdx.x;   // 81920
    int k = idx % 40; int r = idx / 40;
    int o  = r & 127; r >>= 7;
    int hl = r & 1;   r >>= 1;
    int ch = r & 3;   int og = r >> 2;
    float v = 0.f;
    if (k < 32) v = w[(og*128+o)*C1_ + ch*32 + k];
    __half hi = __float2half_rn(v);
    g_wh[idx] = (hl == 0) ? hi : __float2half_rn(v - __half2float(hi));
}

// ---------------------------------------------------------------------------
// K1: y = silu(bn(conv1x1(x))) via 3-pass fp16 MMA (w hi/lo, x hi/lo)
//     tile: 128 o x 128 px, K=128 in 4 chunks of 32. 8 warps = 4M x 2N.
//     Writes fp16 g_ym[b][px][ci] + fp32 partial sums for InstanceNorm stats.
// ---------------------------------------------------------------------------
__global__ __launch_bounds__(256)
void k1_mma(const float* __restrict__ x,
            const float* __restrict__ bng, const float* __restrict__ bnb,
            const float* __restrict__ bnm, const float* __restrict__ bnv)
{
    __shared__ __align__(16) union {
        struct { __half Ah[5120], Al[5120], Bh[5120], Bl[5120]; } st;  // 40 KB
        __half outb[128*136];                                          // 34.8 KB
    } u;
    __shared__ float wsum[2][128], wsum2[2][128];

    const int b  = blockIdx.z;
    const int og = blockIdx.y;
    const int p0 = blockIdx.x * 128;
    const int tid = threadIdx.x;
    const int lane = tid & 31, warp = tid >> 5;
    const int warp_m = warp & 3, warp_n = warp >> 2;
    const int px_l = tid & 127, cblk = tid >> 7;

    float acc[2][8][4];
#pragma unroll
    for (int mr = 0; mr < 2; ++mr)
#pragma unroll
        for (int nr = 0; nr < 8; ++nr)
#pragma unroll
            for (int j = 0; j < 4; ++j) acc[mr][nr][j] = 0.f;

    for (int ch = 0; ch < 4; ++ch) {
        // stage A: hi+lo 2*5120 halves = 1280 int4, contiguous from g_wh
        const int4* asrc = (const int4*)(g_wh + (size_t)(og*4 + ch)*2*5120);
        int4* adst = (int4*)u.st.Ah;
#pragma unroll
        for (int i = 0; i < 5; ++i)
            adst[tid + 256*i] = asrc[tid + 256*i];

        // stage B: x [32c x 128px] -> transposed hi/lo [px][c]
        __half hbuf[16], lbuf[16];
#pragma unroll
        for (int j = 0; j < 16; ++j) {
            float v = x[((size_t)(b*C1_ + ch*32 + cblk*16 + j))*P_ + p0 + px_l];
            __half h = __float2half_rn(v);
            hbuf[j] = h;
            lbuf[j] = __float2half_rn(v - __half2float(h));
        }
        *(int4*)&u.st.Bh[px_l*40 + cblk*16]     = ((int4*)hbuf)[0];
        *(int4*)&u.st.Bh[px_l*40 + cblk*16 + 8] = ((int4*)hbuf)[1];
        *(int4*)&u.st.Bl[px_l*40 + cblk*16]     = ((int4*)lbuf)[0];
        *(int4*)&u.st.Bl[px_l*40 + cblk*16 + 8] = ((int4*)lbuf)[1];
        __syncthreads();

#pragma unroll
        for (int ks = 0; ks < 2; ++ks) {
            const int kb = ks*16 + 2*(lane&3);
            uint32_t ah[2][4], al[2][4];
#pragma unroll
            for (int mr = 0; mr < 2; ++mr) {
                int o = warp_m*32 + mr*16 + (lane>>2);
                const uint32_t* ph  = (const uint32_t*)&u.st.Ah[o*40 + kb];
                const uint32_t* ph8 = (const uint32_t*)&u.st.Ah[(o+8)*40 + kb];
                const uint32_t* pl  = (const uint32_t*)&u.st.Al[o*40 + kb];
                const uint32_t* pl8 = (const uint32_t*)&u.st.Al[(o+8)*40 + kb];
                ah[mr][0] = ph[0];  ah[mr][1] = ph8[0];  ah[mr][2] = ph[4];  ah[mr][3] = ph8[4];
                al[mr][0] = pl[0];  al[mr][1] = pl8[0];  al[mr][2] = pl[4];  al[mr][3] = pl8[4];
            }
            uint32_t bh[8][2], bl[8][2];
#pragma unroll
            for (int nr = 0; nr < 8; ++nr) {
                int px = warp_n*64 + nr*8 + (lane>>2);
                const uint32_t* qh = (const uint32_t*)&u.st.Bh[px*40 + ks*16 + 2*(lane&3)];
                const uint32_t* ql = (const uint32_t*)&u.st.Bl[px*40 + ks*16 + 2*(lane&3)];
                bh[nr][0] = qh[0];  bh[nr][1] = qh[4];
                bl[nr][0] = ql[0];  bl[nr][1] = ql[4];
            }
#pragma unroll
            for (int mr = 0; mr < 2; ++mr)
#pragma unroll
                for (int nr = 0; nr < 8; ++nr) {
                    mma16816(acc[mr][nr], ah[mr], bh[nr]);
                    mma16816(acc[mr][nr], al[mr], bh[nr]);
                    mma16816(acc[mr][nr], ah[mr], bl[nr]);
                }
        }
        __syncthreads();
    }

    // Epilogue: bn + silu (fp32), partial sums, fp16 staging [px][o]
#pragma unroll
    for (int mr = 0; mr < 2; ++mr) {
        const int ola = warp_m*32 + mr*16 + (lane>>2);
        const int olb = ola + 8;
        const int o_a = og*128 + ola, o_b = og*128 + olb;
        float sa = bng[o_a] * rsqrtf(bnv[o_a] + EPS_);
        float ta = bnb[o_a] - bnm[o_a]*sa;
        float sb = bng[o_b] * rsqrtf(bnv[o_b] + EPS_);
        float tb = bnb[o_b] - bnm[o_b]*sb;
        float sA = 0.f, sA2 = 0.f, sB = 0.f, sB2 = 0.f;
#pragma unroll
        for (int nr = 0; nr < 8; ++nr) {
#pragma unroll
            for (int c = 0; c < 2; ++c) {
                int px = warp_n*64 + nr*8 + 2*(lane&3) + c;
                float va = acc[mr][nr][c]*sa + ta;
                va = va / (1.f + expf(-va));
                sA += va; sA2 += va*va;
                u.outb[px*136 + ola] = __float2half_rn(va);
                float vb = acc[mr][nr][2+c]*sb + tb;
                vb = vb / (1.f + expf(-vb));
                sB += vb; sB2 += vb*vb;
                u.outb[px*136 + olb] = __float2half_rn(vb);
            }
        }
        // quad reduce (lanes sharing lane>>2)
#pragma unroll
        for (int off = 1; off <= 2; off <<= 1) {
            sA  += __shfl_xor_sync(0xffffffffu, sA,  off);
            sA2 += __shfl_xor_sync(0xffffffffu, sA2, off);
            sB  += __shfl_xor_sync(0xffffffffu, sB,  off);
            sB2 += __shfl_xor_sync(0xffffffffu, sB2, off);
        }
        if ((lane & 3) == 0) {
            wsum [warp_n][ola] = sA;  wsum2[warp_n][ola] = sA2;
            wsum [warp_n][olb] = sB;  wsum2[warp_n][olb] = sB2;
        }
    }
    __syncthreads();
    if (tid < 128) {
        float s  = wsum [0][tid] + wsum [1][tid];
        float s2 = wsum2[0][tid] + wsum2[1][tid];
        g_ps [blockIdx.x*(B_*C2_) + b*C2_ + og*128 + tid] = s;
        g_ps2[blockIdx.x*(B_*C2_) + b*C2_ + og*128 + tid] = s2;
    }
    // write g_ym coalesced: 2048 int4
#pragma unroll
    for (int it = 0; it < 8; ++it) {
        int l = tid + 256*it;
        int px = l >> 4, seg = l & 15;
        *(int4*)(g_ym + ((size_t)b*P_ + p0 + px)*C2_ + og*128 + seg*8) =
            *(const int4*)&u.outb[px*136 + seg*8];
    }
}

// ---------------------------------------------------------------------------
// K2: finalize stats (coalesced reads)
// ---------------------------------------------------------------------------
__global__ void k2_fin()
{
    int idx = blockIdx.x*256 + threadIdx.x;   // b*C2 + o
    float s = 0.f, s2 = 0.f;
    for (int t = 0; t < 50; ++t) {
        s  += g_ps [t*(B_*C2_) + idx];
        s2 += g_ps2[t*(B_*C2_) + idx];
    }
    float mu  = s  * (1.f / P_);
    float var = s2 * (1.f / P_) - mu*mu;
    float rs  = rsqrtf(fmaxf(var, 0.f) + EPS_);
    g_mu[idx]   = mu;
    g_rstd[idx] = rs;
    g_mr[idx]   = mu * rs;
}

// ---------------------------------------------------------------------------
// K3: attention (one warp per sample)
// ---------------------------------------------------------------------------
__global__ void k3_attn(const float* __restrict__ fc1w, const float* __restrict__ fc1b,
                        const float* __restrict__ fc2w, const float* __restrict__ fc2b)
{
    const int b = blockIdx.x, lane = threadIdx.x;
    float s0 = 0.f, s1 = 0.f, s2 = 0.f, s3 = 0.f;
    for (int c = lane; c < C2_; c += 32) {
        float pv = g_mu[b*C2_ + c];
        s0 += pv * fc1w[0*C2_ + c];
        s1 += pv * fc1w[1*C2_ + c];
        s2 += pv * fc1w[2*C2_ + c];
        s3 += pv * fc1w[3*C2_ + c];
    }
#pragma unroll
    for (int off = 16; off; off >>= 1) {
        s0 += __shfl_down_sync(0xffffffffu, s0, off);
        s1 += __shfl_down_sync(0xffffffffu, s1, off);
        s2 += __shfl_down_sync(0xffffffffu, s2, off);
        s3 += __shfl_down_sync(0xffffffffu, s3, off);
    }
    if (lane == 0) {
        float a[4];
        a[0] = fmaxf(s0 + fc1b[0], 0.f);
        a[1] = fmaxf(s1 + fc1b[1], 0.f);
        a[2] = fmaxf(s2 + fc1b[2], 0.f);
        a[3] = fmaxf(s3 + fc1b[3], 0.f);
        float l[4];
#pragma unroll
        for (int j = 0; j < 4; ++j)
            l[j] = a[0]*fc2w[j*4+0] + a[1]*fc2w[j*4+1] + a[2]*fc2w[j*4+2] + a[3]*fc2w[j*4+3] + fc2b[j];
        float m = fmaxf(fmaxf(l[0], l[1]), fmaxf(l[2], l[3]));
        float e[4], den = 0.f;
#pragma unroll
        for (int j = 0; j < 4; ++j) { e[j] = expf(l[j] - m); den += e[j]; }
        float inv = 1.f / den;
#pragma unroll
        for (int j = 0; j < 4; ++j) g_attn[b*4 + j] = e[j] * inv;
    }
}

// ---------------------------------------------------------------------------
// K4: aggregate weights, fold rstd, permute to MMA layout via smem
// block per (ch, og, b); coalesced dyw reads (72 contiguous floats per o)
// ---------------------------------------------------------------------------
__global__ __launch_bounds__(256)
void k4_aggw(const float* __restrict__ dyw)
{
    __shared__ float s[128*73];
    const int ch = blockIdx.x, og = blockIdx.y, b = blockIdx.z;
    const float a0 = g_attn[b*4+0], a1 = g_attn[b*4+1];
    const float a2 = g_attn[b*4+2], a3 = g_attn[b*4+3];
    const size_t ks = (size_t)C2_*C2_*9;

#pragma unroll
    for (int i = 0; i < 36; ++i) {
        int idx = threadIdx.x + 256*i;           // < 9216
        int o = idx / 72, r = idx - o*72;        // r = ci_sub*9 + q
        size_t base = (size_t)(og*128 + o)*2304 + ch*72 + r;
        float v = a0*dyw[base] + a1*dyw[base+ks] + a2*dyw[base+2*ks] + a3*dyw[base+3*ks];
        int ci = ch*8 + r/9;
        v *= g_rstd[b*C2_ + ci];
        s[o*73 + r] = v;
    }
    __syncthreads();
    __half* outp = g_wm + ((size_t)((b*2 + og)*NCH + ch))*(size_t)(128*KCH);
#pragma unroll
    for (int i = 0; i < 44; ++i) {
        int idx = threadIdx.x + 256*i;           // < 11264
        int o = idx / 88, k = idx - o*88;        // k = q*8 + ci_sub
        float v = (k < 72) ? s[o*73 + (k&7)*9 + (k>>3)] : 0.f;
        outp[idx] = __float2half_rn(v);
    }
}

// K4b: agg_b[b,o]
__global__ void k4_aggb(const float* __restrict__ dyb)
{
    int idx = blockIdx.x*256 + threadIdx.x;   // 4096
    int b = idx >> 8, o = idx & 255;
    float v = 0.f;
#pragma unroll
    for (int k = 0; k < 4; ++k) v += g_attn[b*4+k] * dyb[k*C2_ + o];
    g_aggb[idx] = v;
}

// K4c: Cq[b,o,q] = sum_ci w_agg[b,o,ci,q]*mu[ci]*rstd[ci];  Cqt = sum_q Cq
__global__ __launch_bounds__(288)
void k4c_cq(const float* __restrict__ dyw)
{
    __shared__ float sh[32][9];
    __shared__ float shc[9];
    const int o = blockIdx.x, b = blockIdx.y;
    const int tid = threadIdx.x;
    const int ciw = tid / 9, q = tid - ciw*9;

    const float a0 = g_attn[b*4+0], a1 = g_attn[b*4+1];
    const float a2 = g_attn[b*4+2], a3 = g_attn[b*4+3];
    const size_t ks = (size_t)C2_*C2_*9;
    float acc = 0.f;
    for (int ci = ciw; ci < C2_; ci += 32) {
        size_t base = ((size_t)o*C2_ + ci)*9 + q;
        float wv = a0*dyw[base] + a1*dyw[base+ks] + a2*dyw[base+2*ks] + a3*dyw[base+3*ks];
        acc += wv * g_mr[b*C2_ + ci];
    }
    sh[ciw][q] = acc;
    __syncthreads();
    if (tid < 9) {
        float s = 0.f;
#pragma unroll
        for (int i = 0; i < 32; ++i) s += sh[i][tid];
        g_cq[(b*C2_+o)*9 + tid] = s;
        shc[tid] = s;
    }
    __syncthreads();
    if (tid == 0) {
        float s = 0.f;
#pragma unroll
        for (int i = 0; i < 9; ++i) s += shc[i];
        g_cqt[b*C2_+o] = s;
    }
}

// ---------------------------------------------------------------------------
// K5: tensor-core implicit-GEMM 3x3 conv, 1-pass fp16
// ---------------------------------------------------------------------------
__global__ __launch_bounds__(256)
void k5_mma(const float* __restrict__ g1, const float* __restrict__ b1,
            const float* __restrict__ m1, const float* __restrict__ v1,
            float* __restrict__ out)
{
    __shared__ __align__(16) __half As[128*KCH];   // 22.5 KB
    __shared__ __align__(16) __half Bs[180*8];     // 2.9 KB

    const int b    = blockIdx.z;
    const int og   = blockIdx.y;
    const int tile = blockIdx.x;                 // 0..49
    const int h0 = (tile/5)*8, w0 = (tile%5)*16;
    const int tid  = threadIdx.x;
    const int lane = tid & 31, warp = tid >> 5;
    const int warp_m = warp & 3, warp_n = warp >> 2;

    float acc[2][8][4];
#pragma unroll
    for (int mr = 0; mr < 2; ++mr)
#pragma unroll
        for (int nr = 0; nr < 8; ++nr)
#pragma unroll
            for (int j = 0; j < 4; ++j) acc[mr][nr][j] = 0.f;

    const __half* wsrc = g_wm + (((size_t)b*2 + og)*NCH)*(size_t)(128*KCH);

    const int st_px = tid;
    const int st_r = st_px/18, st_c = st_px - st_r*18;
    const int gh = h0 + st_r - 1, gw = w0 + st_c - 1;
    const bool st_ok = (tid < 180) && gh >= 0 && gh < H_ && gw >= 0 && gw < W_;
    const int ghc = max(0, min(H_-1, gh)), gwc = max(0, min(W_-1, gw));
    const size_t st_src0 = ((size_t)b*P_ + ghc*W_ + gwc)*(size_t)C2_;

    const int DY0[5] = {0,0,1,2,2}, DX0[5] = {0,2,1,0,2};
    const int DY1[5] = {0,1,1,2,0}, DX1[5] = {1,0,2,1,0};

    for (int ch = 0; ch < NCH; ++ch) {
        const int4* asrc = (const int4*)(wsrc + (size_t)ch*128*KCH);
        int4* adst = (int4*)&As[0];
#pragma unroll
        for (int i = 0; i < 6; ++i) {
            int idx = tid + 256*i;
            if (idx < 1408) adst[idx] = asrc[idx];
        }
        if (tid < 180) {
            int4 vv = make_int4(0,0,0,0);
            if (st_ok) vv = *(const int4*)(g_ym + st_src0 + ch*8);
            *(int4*)&Bs[st_px*8] = vv;
        }
        __syncthreads();

#pragma unroll
        for (int s = 0; s < 5; ++s) {
            uint32_t ah[2][4];
            const int kb = 16*s + 2*(lane&3);
#pragma unroll
            for (int mr = 0; mr < 2; ++mr) {
                int o = warp_m*32 + mr*16 + (lane>>2);
                const uint32_t* ph  = (const uint32_t*)&As[o*KCH + kb];
                const uint32_t* ph8 = (const uint32_t*)&As[(o+8)*KCH + kb];
                ah[mr][0] = ph[0];  ah[mr][1] = ph8[0];  ah[mr][2] = ph[4];  ah[mr][3] = ph8[4];
            }
            const int dy0 = DY0[s], dx0 = DX0[s], dy1 = DY1[s], dx1 = DX1[s];
            uint32_t bh[8][2];
#pragma unroll
            for (int nr = 0; nr < 8; ++nr) {
                int pr = warp_n*4 + (nr>>1);
                int pc = (nr&1)*8 + (lane>>2);
                int i0 = ((pr+dy0)*18 + pc+dx0)*8 + 2*(lane&3);
                int i1 = ((pr+dy1)*18 + pc+dx1)*8 + 2*(lane&3);
                bh[nr][0] = *(const uint32_t*)&Bs[i0];
                bh[nr][1] = *(const uint32_t*)&Bs[i1];
            }
#pragma unroll
            for (int mr = 0; mr < 2; ++mr)
#pragma unroll
                for (int nr = 0; nr < 8; ++nr)
                    mma16816(acc[mr][nr], ah[mr], bh[nr]);
        }
        __syncthreads();
    }

    const int obase = og*128 + warp_m*32;
#pragma unroll
    for (int mr = 0; mr < 2; ++mr) {
        const int o_a = obase + mr*16 + (lane>>2);
        const int o_b = o_a + 8;
        float sA = __ldg(&g1[o_a]) * rsqrtf(__ldg(&v1[o_a]) + EPS_);
        float offA = (__ldg(&g_aggb[b*C2_+o_a]) - g_cqt[b*C2_+o_a] - __ldg(&m1[o_a]))*sA + __ldg(&b1[o_a]);
        float sB = __ldg(&g1[o_b]) * rsqrtf(__ldg(&v1[o_b]) + EPS_);
        float offB = (__ldg(&g_aggb[b*C2_+o_b]) - g_cqt[b*C2_+o_b] - __ldg(&m1[o_b]))*sB + __ldg(&b1[o_b]);
#pragma unroll
        for (int nr = 0; nr < 8; ++nr) {
            int pr = warp_n*4 + (nr>>1);
            int pc = (nr&1)*8 + 2*(lane&3);
            int h = h0 + pr, w1 = w0 + pc, w2 = w1 + 1;
            float fA1 = 0.f, fA2 = 0.f, fB1 = 0.f, fB2 = 0.f;
            if (h == 0 || h == H_-1 || w1 == 0 || w2 == W_-1) {
#pragma unroll
                for (int q = 0; q < 9; ++q) {
                    int dy = q/3 - 1, dx = q - (q/3)*3 - 1;
                    bool ro = (unsigned)(h+dy) >= (unsigned)H_;
                    bool c1 = ro || (unsigned)(w1+dx) >= (unsigned)W_;
                    bool c2 = ro || (unsigned)(w2+dx) >= (unsigned)W_;
                    if (c1 | c2) {
                        float ca = g_cq[(b*C2_+o_a)*9 + q];
                        float cb = g_cq[(b*C2_+o_b)*9 + q];
                        if (c1) { fA1 += ca; fB1 += cb; }
                        if (c2) { fA2 += ca; fB2 += cb; }
                    }
                }
            }
            size_t po = (size_t)h*W_ + w1;
            float2 vA, vB;
            vA.x = (acc[mr][nr][0]+fA1)*sA + offA;  vA.y = (acc[mr][nr][1]+fA2)*sA + offA;
            vB.x = (acc[mr][nr][2]+fB1)*sB + offB;  vB.y = (acc[mr][nr][3]+fB2)*sB + offB;
            *(float2*)&out[((size_t)(b*C2_+o_a))*P_ + po] = vA;
            *(float2*)&out[((size_t)(b*C2_+o_b))*P_ + po] = vB;
        }
    }
}

// ---------------------------------------------------------------------------
extern "C" void kernel_launch(void* const* d_in, const int* in_sizes, int n_in,
                              void* d_out, int out_size)
{
    const float* x      = (const float*)d_in[0];
    const float* conv1w = (const float*)d_in[1];
    const float* bng    = (const float*)d_in[2];
    const float* bnb    = (const float*)d_in[3];
    const float* bnm    = (const float*)d_in[4];
    const float* bnv    = (const float*)d_in[5];
    const float* fc1w   = (const float*)d_in[6];
    const float* fc1b   = (const float*)d_in[7];
    const float* fc2w   = (const float*)d_in[8];
    const float* fc2b   = (const float*)d_in[9];
    const float* dyw    = (const float*)d_in[10];
    const float* dyb    = (const float*)d_in[11];
    const float* g1     = (const float*)d_in[12];
    const float* b1     = (const float*)d_in[13];
    const float* m1     = (const float*)d_in[14];
    const float* v1     = (const float*)d_in[15];
    float* out = (float*)d_out;

    k0_wsplit<<<320, 256>>>(conv1w);
    k1_mma<<<dim3(50, 2, B_), 256>>>(x, bng, bnb, bnm, bnv);
    k2_fin<<<B_*C2_/256, 256>>>();
    k3_attn<<<B_, 32>>>(fc1w, fc1b, fc2w, fc2b);
    k4_aggw<<<dim3(NCH, 2, B_), 256>>>(dyw);
    k4_aggb<<<B_*C2_/256, 256>>>(dyb);
    k4c_cq<<<dim3(C2_, B_), 288>>>(dyw);
    k5_mma<<<dim3(50, 2, B_), 256>>>(g1, b1, m1, v1, out);
}

// round 10
// speedup vs baseline: 11.6741x; 1.1465x over previous
#include <cuda_runtime.h>
#include <cuda_fp16.h>
#include <cstdint>
#include <cstddef>

// Problem constants
#define B_  16
#define C1_ 128
#define C2_ 256
#define H_  80
#define W_  80
#define P_  (H_*W_)           // 6400
#define EPS_ 1e-5f

// k5 A layout: [b][og2][chunk16][o128][144]  (chunk = 16-ci block, k = q*16+ci_sub)
#define K5_CH 16
#define K5_K  144
#define ACH   152             // A smem row stride (halves) - bank-conflict free
#define BROW  40              // B smem row stride (halves) - bank-conflict free
#define K5_SMEM (128*ACH*2 + 180*BROW*2)   // 38912 + 14400 = 53312

// Scratch (device globals)
__device__ float g_ps [B_*C2_*128];       // [tile][b*C2+o] partial sums (50 tiles)
__device__ float g_ps2[B_*C2_*128];
__device__ float g_mu[B_*C2_];
__device__ float g_rstd[B_*C2_];
__device__ float g_mr[B_*C2_];
__device__ float g_attn[B_*4];
__device__ float g_aggb[B_*C2_];
__device__ float g_cq [B_*C2_*9];
__device__ float g_cqt[B_*C2_];
// MMA weights (rstd-folded fp16): [b][og2][chunk16][o128][144]  (~18.9 MB)
__device__ __align__(16) __half g_wm[(size_t)B_*2*K5_CH*128*K5_K];
// MMA input y (fp16): [b][pix6400][ci256] (~52 MB)
__device__ __align__(16) __half g_ym[(size_t)B_*P_*C2_];

__device__ __forceinline__ void mma16816(float* d, const uint32_t* a, const uint32_t* bb)
{
    asm volatile(
        "mma.sync.aligned.m16n8k16.row.col.f32.f16.f16.f32 "
        "{%0,%1,%2,%3}, {%4,%5,%6,%7}, {%8,%9}, {%0,%1,%2,%3};"
        : "+f"(d[0]), "+f"(d[1]), "+f"(d[2]), "+f"(d[3])
        : "r"(a[0]), "r"(a[1]), "r"(a[2]), "r"(a[3]), "r"(bb[0]), "r"(bb[1]));
}

// ---------------------------------------------------------------------------
// K1: conv1x1 + bn + silu via 1-pass fp16 mma.sync (w and x converted inline)
//     tile: 128 o x 128 px, K=128 in 4 chunks of 32. 8 warps = 4M x 2N.
//     Writes fp16 g_ym[b][px][ci] + fp32 partial sums for InstanceNorm stats.
// ---------------------------------------------------------------------------
__global__ __launch_bounds__(256)
void k1_mma(const float* __restrict__ x, const float* __restrict__ w,
            const float* __restrict__ bng, const float* __restrict__ bnb,
            const float* __restrict__ bnm, const float* __restrict__ bnv)
{
    __shared__ __align__(16) union {
        struct { __half Ah[5120], Bh[5120]; } st;   // 20 KB
        __half outb[128*136];                        // 34.8 KB
    } u;
    __shared__ float wsum[2][128], wsum2[2][128];

    const int b  = blockIdx.z;
    const int og = blockIdx.y;
    const int p0 = blockIdx.x * 128;
    const int tid = threadIdx.x;
    const int lane = tid & 31, warp = tid >> 5;
    const int warp_m = warp & 3, warp_n = warp >> 2;
    const int px_l = tid & 127, cblk = tid >> 7;

    float acc[2][8][4];
#pragma unroll
    for (int mr = 0; mr < 2; ++mr)
#pragma unroll
        for (int nr = 0; nr < 8; ++nr)
#pragma unroll
            for (int j = 0; j < 4; ++j) acc[mr][nr][j] = 0.f;

    for (int ch = 0; ch < 4; ++ch) {
        // stage A: w [128o x 32c] fp32 -> fp16, rows of 40 (padded)
#pragma unroll
        for (int it = 0; it < 16; ++it) {
            int idx = tid + 256*it;              // < 4096
            int o = idx >> 5, c = idx & 31;
            u.st.Ah[o*40 + c] = __float2half_rn(w[(og*128+o)*C1_ + ch*32 + c]);
        }
        // stage B: x [32c x 128px] -> transposed fp16 [px][c]
        __half hbuf[16];
#pragma unroll
        for (int j = 0; j < 16; ++j)
            hbuf[j] = __float2half_rn(
                x[((size_t)(b*C1_ + ch*32 + cblk*16 + j))*P_ + p0 + px_l]);
        *(int4*)&u.st.Bh[px_l*40 + cblk*16]     = ((int4*)hbuf)[0];
        *(int4*)&u.st.Bh[px_l*40 + cblk*16 + 8] = ((int4*)hbuf)[1];
        __syncthreads();

#pragma unroll
        for (int ks = 0; ks < 2; ++ks) {
            const int kb = ks*16 + 2*(lane&3);
            uint32_t ah[2][4];
#pragma unroll
            for (int mr = 0; mr < 2; ++mr) {
                int o = warp_m*32 + mr*16 + (lane>>2);
                const uint32_t* ph  = (const uint32_t*)&u.st.Ah[o*40 + kb];
                const uint32_t* ph8 = (const uint32_t*)&u.st.Ah[(o+8)*40 + kb];
                ah[mr][0] = ph[0];  ah[mr][1] = ph8[0];  ah[mr][2] = ph[4];  ah[mr][3] = ph8[4];
            }
            uint32_t bh[8][2];
#pragma unroll
            for (int nr = 0; nr < 8; ++nr) {
                int px = warp_n*64 + nr*8 + (lane>>2);
                const uint32_t* qh = (const uint32_t*)&u.st.Bh[px*40 + ks*16 + 2*(lane&3)];
                bh[nr][0] = qh[0];  bh[nr][1] = qh[4];
            }
#pragma unroll
            for (int mr = 0; mr < 2; ++mr)
#pragma unroll
                for (int nr = 0; nr < 8; ++nr)
                    mma16816(acc[mr][nr], ah[mr], bh[nr]);
        }
        __syncthreads();
    }

    // Epilogue: bn + silu (fp32), partial sums, fp16 staging [px][o]
#pragma unroll
    for (int mr = 0; mr < 2; ++mr) {
        const int ola = warp_m*32 + mr*16 + (lane>>2);
        const int olb = ola + 8;
        const int o_a = og*128 + ola, o_b = og*128 + olb;
        float sa = bng[o_a] * rsqrtf(bnv[o_a] + EPS_);
        float ta = bnb[o_a] - bnm[o_a]*sa;
        float sb = bng[o_b] * rsqrtf(bnv[o_b] + EPS_);
        float tb = bnb[o_b] - bnm[o_b]*sb;
        float sA = 0.f, sA2 = 0.f, sB = 0.f, sB2 = 0.f;
#pragma unroll
        for (int nr = 0; nr < 8; ++nr) {
#pragma unroll
            for (int c = 0; c < 2; ++c) {
                int px = warp_n*64 + nr*8 + 2*(lane&3) + c;
                float va = acc[mr][nr][c]*sa + ta;
                va = va / (1.f + expf(-va));
                sA += va; sA2 += va*va;
                u.outb[px*136 + ola] = __float2half_rn(va);
                float vb = acc[mr][nr][2+c]*sb + tb;
                vb = vb / (1.f + expf(-vb));
                sB += vb; sB2 += vb*vb;
                u.outb[px*136 + olb] = __float2half_rn(vb);
            }
        }
#pragma unroll
        for (int off = 1; off <= 2; off <<= 1) {
            sA  += __shfl_xor_sync(0xffffffffu, sA,  off);
            sA2 += __shfl_xor_sync(0xffffffffu, sA2, off);
            sB  += __shfl_xor_sync(0xffffffffu, sB,  off);
            sB2 += __shfl_xor_sync(0xffffffffu, sB2, off);
        }
        if ((lane & 3) == 0) {
            wsum [warp_n][ola] = sA;  wsum2[warp_n][ola] = sA2;
            wsum [warp_n][olb] = sB;  wsum2[warp_n][olb] = sB2;
        }
    }
    __syncthreads();
    if (tid < 128) {
        float s  = wsum [0][tid] + wsum [1][tid];
        float s2 = wsum2[0][tid] + wsum2[1][tid];
        g_ps [blockIdx.x*(B_*C2_) + b*C2_ + og*128 + tid] = s;
        g_ps2[blockIdx.x*(B_*C2_) + b*C2_ + og*128 + tid] = s2;
    }
#pragma unroll
    for (int it = 0; it < 8; ++it) {
        int l = tid + 256*it;
        int px = l >> 4, seg = l & 15;
        *(int4*)(g_ym + ((size_t)b*P_ + p0 + px)*C2_ + og*128 + seg*8) =
            *(const int4*)&u.outb[px*136 + seg*8];
    }
}

// ---------------------------------------------------------------------------
// K2: finalize stats + fused attention (one block per sample)
// ---------------------------------------------------------------------------
__global__ __launch_bounds__(256)
void k2_fin(const float* __restrict__ fc1w, const float* __restrict__ fc1b,
            const float* __restrict__ fc2w, const float* __restrict__ fc2b)
{
    __shared__ float pooled[256];
    const int b = blockIdx.x, o = threadIdx.x;
    const int idx = b*C2_ + o;
    float s = 0.f, s2 = 0.f;
    for (int t = 0; t < 50; ++t) {
        s  += g_ps [t*(B_*C2_) + idx];
        s2 += g_ps2[t*(B_*C2_) + idx];
    }
    float mu  = s  * (1.f / P_);
    float var = s2 * (1.f / P_) - mu*mu;
    float rs  = rsqrtf(fmaxf(var, 0.f) + EPS_);
    g_mu[idx]   = mu;
    g_rstd[idx] = rs;
    g_mr[idx]   = mu * rs;
    pooled[o] = mu;
    __syncthreads();

    if (o < 32) {
        const int lane = o;
        float s0 = 0.f, s1 = 0.f, s2a = 0.f, s3 = 0.f;
        for (int c = lane; c < C2_; c += 32) {
            float pv = pooled[c];
            s0  += pv * fc1w[0*C2_ + c];
            s1  += pv * fc1w[1*C2_ + c];
            s2a += pv * fc1w[2*C2_ + c];
            s3  += pv * fc1w[3*C2_ + c];
        }
#pragma unroll
        for (int off = 16; off; off >>= 1) {
            s0  += __shfl_down_sync(0xffffffffu, s0,  off);
            s1  += __shfl_down_sync(0xffffffffu, s1,  off);
            s2a += __shfl_down_sync(0xffffffffu, s2a, off);
            s3  += __shfl_down_sync(0xffffffffu, s3,  off);
        }
        if (lane == 0) {
            float a[4];
            a[0] = fmaxf(s0  + fc1b[0], 0.f);
            a[1] = fmaxf(s1  + fc1b[1], 0.f);
            a[2] = fmaxf(s2a + fc1b[2], 0.f);
            a[3] = fmaxf(s3  + fc1b[3], 0.f);
            float l[4];
#pragma unroll
            for (int j = 0; j < 4; ++j)
                l[j] = a[0]*fc2w[j*4+0] + a[1]*fc2w[j*4+1] + a[2]*fc2w[j*4+2] + a[3]*fc2w[j*4+3] + fc2b[j];
            float m = fmaxf(fmaxf(l[0], l[1]), fmaxf(l[2], l[3]));
            float e[4], den = 0.f;
#pragma unroll
            for (int j = 0; j < 4; ++j) { e[j] = expf(l[j] - m); den += e[j]; }
            float inv = 1.f / den;
#pragma unroll
            for (int j = 0; j < 4; ++j) g_attn[b*4 + j] = e[j] * inv;
        }
    }
}

// ---------------------------------------------------------------------------
// K4: aggregate weights, fold rstd, emit k5 A layout [chunk][o][q*16+ci_sub]
// block per (ch=8ci, og, b); coalesced dyw reads; int4 writes
// ---------------------------------------------------------------------------
__global__ __launch_bounds__(256)
void k4_aggw(const float* __restrict__ dyw)
{
    __shared__ float s[128*73];
    const int ch = blockIdx.x, og = blockIdx.y, b = blockIdx.z;
    const int tid = threadIdx.x;
    const float a0 = g_attn[b*4+0], a1 = g_attn[b*4+1];
    const float a2 = g_attn[b*4+2], a3 = g_attn[b*4+3];
    const size_t ks = (size_t)C2_*C2_*9;

#pragma unroll
    for (int i = 0; i < 36; ++i) {
        int idx = tid + 256*i;                    // < 9216
        int o = idx / 72, r = idx - o*72;         // r = ci_sub*9 + q
        size_t base = (size_t)(og*128 + o)*2304 + ch*72 + r;
        float v = a0*dyw[base] + a1*dyw[base+ks] + a2*dyw[base+2*ks] + a3*dyw[base+3*ks];
        int ci = ch*8 + r/9;
        v *= g_rstd[b*C2_ + ci];
        s[o*73 + r] = v;
    }
    __syncthreads();

    __half* obase = g_wm + ((size_t)(b*2 + og)*K5_CH + (ch>>1))*(size_t)(128*K5_K)
                  + (ch&1)*8;
#pragma unroll
    for (int i = 0; i < 5; ++i) {
        int idx = tid + 256*i;                    // < 1152 = 128 o * 9 q
        if (idx < 1152) {
            int o = idx & 127, q = idx >> 7;
            alignas(16) __half hv[8];
#pragma unroll
            for (int cs = 0; cs < 8; ++cs)
                hv[cs] = __float2half_rn(s[o*73 + cs*9 + q]);
            *(int4*)(obase + o*K5_K + q*16) = *(const int4*)hv;
        }
    }
}

// K4c: Cq[b,o,q], Cqt, and agg_b (fused)
__global__ __launch_bounds__(288)
void k4c_cq(const float* __restrict__ dyw, const float* __restrict__ dyb)
{
    __shared__ float sh[32][9];
    __shared__ float shc[9];
    const int o = blockIdx.x, b = blockIdx.y;
    const int tid = threadIdx.x;
    const int ciw = tid / 9, q = tid - ciw*9;

    const float a0 = g_attn[b*4+0], a1 = g_attn[b*4+1];
    const float a2 = g_attn[b*4+2], a3 = g_attn[b*4+3];
    const size_t ks = (size_t)C2_*C2_*9;
    float acc = 0.f;
    for (int ci = ciw; ci < C2_; ci += 32) {
        size_t base = ((size_t)o*C2_ + ci)*9 + q;
        float wv = a0*dyw[base] + a1*dyw[base+ks] + a2*dyw[base+2*ks] + a3*dyw[base+3*ks];
        acc += wv * g_mr[b*C2_ + ci];
    }
    sh[ciw][q] = acc;
    __syncthreads();
    if (tid < 9) {
        float sum = 0.f;
#pragma unroll
        for (int i = 0; i < 32; ++i) sum += sh[i][tid];
        g_cq[(b*C2_+o)*9 + tid] = sum;
        shc[tid] = sum;
    }
    __syncthreads();
    if (tid == 0) {
        float sum = 0.f;
#pragma unroll
        for (int i = 0; i < 9; ++i) sum += shc[i];
        g_cqt[b*C2_+o] = sum;
        float vb = a0*dyb[0*C2_+o] + a1*dyb[1*C2_+o] + a2*dyb[2*C2_+o] + a3*dyb[3*C2_+o];
        g_aggb[b*C2_+o] = vb;
    }
}

// ---------------------------------------------------------------------------
// K5: implicit-GEMM 3x3 conv, 1-pass fp16 mma.sync, ZERO padding waste:
// K = 16 chunks x (9 taps x 16 ci) -> 144 k16-steps (minimum MMA count).
// Block: (b, og, 8x16-px tile). 8 warps = 4M x 2N.
// ---------------------------------------------------------------------------
__global__ __launch_bounds__(256)
void k5_mma(const float* __restrict__ g1, const float* __restrict__ b1,
            const float* __restrict__ m1, const float* __restrict__ v1,
            float* __restrict__ out)
{
    extern __shared__ __align__(16) __half sm5[];
    __half* const As = sm5;                 // [128][ACH=152]
    __half* const Bs = sm5 + 128*ACH;       // [180][BROW=40]

    const int b    = blockIdx.z;
    const int og   = blockIdx.y;
    const int tile = blockIdx.x;                 // 0..49
    const int h0 = (tile/5)*8, w0 = (tile%5)*16;
    const int tid  = threadIdx.x;
    const int lane = tid & 31, warp = tid >> 5;
    const int warp_m = warp & 3, warp_n = warp >> 2;

    float acc[2][8][4];
#pragma unroll
    for (int mr = 0; mr < 2; ++mr)
#pragma unroll
        for (int nr = 0; nr < 8; ++nr)
#pragma unroll
            for (int j = 0; j < 4; ++j) acc[mr][nr][j] = 0.f;

    const __half* wsrc = g_wm + (size_t)(b*2 + og)*K5_CH*(size_t)(128*K5_K);

    // B staging: threads 0..179, one halo pixel each (10x18 halo), 16 ci = 2 int4
    const int st_px = tid;
    const int st_r = st_px/18, st_c = st_px - st_r*18;
    const int gh = h0 + st_r - 1, gw = w0 + st_c - 1;
    const bool st_ok = (tid < 180) && gh >= 0 && gh < H_ && gw >= 0 && gw < W_;
    const int ghc = max(0, min(H_-1, gh)), gwc = max(0, min(W_-1, gw));
    const size_t st_src0 = ((size_t)b*P_ + ghc*W_ + gwc)*(size_t)C2_;

    for (int ch = 0; ch < K5_CH; ++ch) {
        // stage A: 128 o x 144 k (36.9KB) -> rows restrided to ACH
        {
            const int4* asrc = (const int4*)(wsrc + (size_t)ch*(128*K5_K));
            int4* adst = (int4*)As;
#pragma unroll
            for (int i = 0; i < 9; ++i) {
                int idx = tid + 256*i;            // < 2304
                int o = idx / 18, j = idx - o*18; // 18 int4 per src row
                adst[o*19 + j] = asrc[idx];       // 19 int4 per dst row (152 halves)
            }
        }
        // stage B: halo pixels x 16 ci of this chunk
        if (tid < 180) {
            int4 v0 = make_int4(0,0,0,0), v1 = make_int4(0,0,0,0);
            if (st_ok) {
                const int4* src = (const int4*)(g_ym + st_src0 + ch*16);
                v0 = src[0]; v1 = src[1];
            }
            *(int4*)&Bs[st_px*BROW]     = v0;
            *(int4*)&Bs[st_px*BROW + 8] = v1;
        }
        __syncthreads();

#pragma unroll
        for (int s = 0; s < 9; ++s) {             // s = tap q
            const int dy = s/3, dx = s - (s/3)*3; // 0..2
            uint32_t ah[2][4];
            const int kb = s*16 + 2*(lane&3);
#pragma unroll
            for (int mr = 0; mr < 2; ++mr) {
                int o = warp_m*32 + mr*16 + (lane>>2);
                const uint32_t* ph  = (const uint32_t*)&As[o*ACH + kb];
                const uint32_t* ph8 = (const uint32_t*)&As[(o+8)*ACH + kb];
                ah[mr][0] = ph[0];  ah[mr][1] = ph8[0];  ah[mr][2] = ph[4];  ah[mr][3] = ph8[4];
            }
            uint32_t bh[8][2];
#pragma unroll
            for (int nr = 0; nr < 8; ++nr) {
                int pr = warp_n*4 + (nr>>1);
                int pc = (nr&1)*8 + (lane>>2);
                const uint32_t* q32 =
                    (const uint32_t*)&Bs[((pr+dy)*18 + pc+dx)*BROW + 2*(lane&3)];
                bh[nr][0] = q32[0];
                bh[nr][1] = q32[4];
            }
#pragma unroll
            for (int mr = 0; mr < 2; ++mr)
#pragma unroll
                for (int nr = 0; nr < 8; ++nr)
                    mma16816(acc[mr][nr], ah[mr], bh[nr]);
        }
        __syncthreads();
    }

    // Epilogue: res = (acc + borderfix)*s + ((aggb - Cqt - m1)*s + b1)
    const int obase = og*128 + warp_m*32;
#pragma unroll
    for (int mr = 0; mr < 2; ++mr) {
        const int o_a = obase + mr*16 + (lane>>2);
        const int o_b = o_a + 8;
        float sA = __ldg(&g1[o_a]) * rsqrtf(__ldg(&v1[o_a]) + EPS_);
        float offA = (__ldg(&g_aggb[b*C2_+o_a]) - g_cqt[b*C2_+o_a] - __ldg(&m1[o_a]))*sA + __ldg(&b1[o_a]);
        float sB = __ldg(&g1[o_b]) * rsqrtf(__ldg(&v1[o_b]) + EPS_);
        float offB = (__ldg(&g_aggb[b*C2_+o_b]) - g_cqt[b*C2_+o_b] - __ldg(&m1[o_b]))*sB + __ldg(&b1[o_b]);
#pragma unroll
        for (int nr = 0; nr < 8; ++nr) {
            int pr = warp_n*4 + (nr>>1);
            int pc = (nr&1)*8 + 2*(lane&3);
            int h = h0 + pr, w1 = w0 + pc, w2 = w1 + 1;
            float fA1 = 0.f, fA2 = 0.f, fB1 = 0.f, fB2 = 0.f;
            if (h == 0 || h == H_-1 || w1 == 0 || w2 == W_-1) {
#pragma unroll
                for (int q = 0; q < 9; ++q) {
                    int dy = q/3 - 1, dx = q - (q/3)*3 - 1;
                    bool ro = (unsigned)(h+dy) >= (unsigned)H_;
                    bool c1 = ro || (unsigned)(w1+dx) >= (unsigned)W_;
                    bool c2 = ro || (unsigned)(w2+dx) >= (unsigned)W_;
                    if (c1 | c2) {
                        float ca = g_cq[(b*C2_+o_a)*9 + q];
                        float cb = g_cq[(b*C2_+o_b)*9 + q];
                        if (c1) { fA1 += ca; fB1 += cb; }
                        if (c2) { fA2 += ca; fB2 += cb; }
                    }
                }
            }
            size_t po = (size_t)h*W_ + w1;
            float2 vA, vB;
            vA.x = (acc[mr][nr][0]+fA1)*sA + offA;  vA.y = (acc[mr][nr][1]+fA2)*sA + offA;
            vB.x = (acc[mr][nr][2]+fB1)*sB + offB;  vB.y = (acc[mr][nr][3]+fB2)*sB + offB;
            *(float2*)&out[((size_t)(b*C2_+o_a))*P_ + po] = vA;
            *(float2*)&out[((size_t)(b*C2_+o_b))*P_ + po] = vB;
        }
    }
}

// ---------------------------------------------------------------------------
extern "C" void kernel_launch(void* const* d_in, const int* in_sizes, int n_in,
                              void* d_out, int out_size)
{
    const float* x      = (const float*)d_in[0];
    const float* conv1w = (const float*)d_in[1];
    const float* bng    = (const float*)d_in[2];
    const float* bnb    = (const float*)d_in[3];
    const float* bnm    = (const float*)d_in[4];
    const float* bnv    = (const float*)d_in[5];
    const float* fc1w   = (const float*)d_in[6];
    const float* fc1b   = (const float*)d_in[7];
    const float* fc2w   = (const float*)d_in[8];
    const float* fc2b   = (const float*)d_in[9];
    const float* dyw    = (const float*)d_in[10];
    const float* dyb    = (const float*)d_in[11];
    const float* g1     = (const float*)d_in[12];
    const float* b1     = (const float*)d_in[13];
    const float* m1     = (const float*)d_in[14];
    const float* v1     = (const float*)d_in[15];
    float* out = (float*)d_out;

    cudaFuncSetAttribute(k5_mma, cudaFuncAttributeMaxDynamicSharedMemorySize, K5_SMEM);

    k1_mma<<<dim3(50, 2, B_), 256>>>(x, conv1w, bng, bnb, bnm, bnv);
    k2_fin<<<B_, 256>>>(fc1w, fc1b, fc2w, fc2b);
    k4_aggw<<<dim3(32, 2, B_), 256>>>(dyw);
    k4c_cq<<<dim3(C2_, B_), 288>>>(dyw, dyb);
    k5_mma<<<dim3(50, 2, B_), 256, K5_SMEM>>>(g1, b1, m1, v1, out);
}